// round 9
// baseline (speedup 1.0000x reference)
#include <cuda_runtime.h>
#include <math.h>
#include <stdint.h>

#define B_  32
#define T_  256
#define E_  256            // V,E,H,K = 50000,256,512,32
#define H_  512
#define K_  32
#define V_  50000
#define G4  2048           // 4*H
#define M_  (T_*B_)        // 8192 tokens
#define NEG_ -10000.0f
#define PITCH 516          // hsm row pitch (floats)

// ---------------- scratch (static device globals; no allocation) -------------
__device__ float g_xwT[2][M_*G4];         // [d][(t*2048+n)*32+b]
__device__ float g_hT [2][M_*H_];         // [d][(t*512+u)*32+b]
__device__ float g_cur[2][2][H_*B_];      // [d][phase][u*32+b]
__device__ float g_feats[B_*T_*K_];       // [m][k], m=b*T+t
__device__ unsigned char g_bp[T_*B_*K_];
__device__ int g_flagA[2][64];            // distributed grid barrier flags

__device__ __forceinline__ float sigm(float x){ return 1.0f/(1.0f+expf(-x)); }

__device__ __forceinline__ void fma2(unsigned long long &acc,
                                     unsigned long long a, unsigned long long b){
    asm("fma.rn.f32x2 %0, %1, %2, %0;" : "+l"(acc) : "l"(a), "l"(b));
}
__device__ __forceinline__ unsigned long long dup2(float a){
    unsigned long long d;
    asm("mov.b64 %0, {%1, %1};" : "=l"(d) : "f"(a));
    return d;
}
__device__ __forceinline__ float collapse2(unsigned long long v){
    float lo, hi;
    asm("mov.b64 {%0, %1}, %2;" : "=f"(lo), "=f"(hi) : "l"(v));
    return lo + hi;
}

__global__ void fill_out(float* out, int n, float val)
{
    int i = blockIdx.x * blockDim.x + threadIdx.x;
    if (i < n) out[i] = val;
}

// ---------------- 1) embedding-gather + input GEMM + fused transpose --------
__global__ void gemm_xw(const void* __restrict__ sentence, int sent64,
                        const float* __restrict__ emb,
                        const float* __restrict__ Wf,
                        const float* __restrict__ Wb,
                        const float* __restrict__ bf,
                        const float* __restrict__ bb)
{
    extern __shared__ float smg[];
    float* As   = smg;            // [8][128]
    float* Bs   = smg + 1024;     // [8][128]
    float* tile = smg + 2048;     // [128][129]

    const int bx = blockIdx.x;    // 0..31 (N tiles)
    const int by = blockIdx.y;    // 0..63 (M tiles)
    const int tid = threadIdx.x;
    const int tx = tid & 15;
    const int ty = tid >> 4;

    const int arow  = tid >> 1;
    const int acol4 = (tid & 1) * 4;
    const int r  = by * 128 + arow;
    const int tt = r >> 5;
    const int bb_ = r & 31;
    long long w64 = sent64 ? ((const long long*)sentence)[bb_ * T_ + tt]
                           : (long long)((const int*)sentence)[bb_ * T_ + tt];
    unsigned int word = (unsigned int)w64;
    if (word >= V_) word = 0;
    const float* aptr = emb + (size_t)word * E_;

    const int brow  = tid >> 1;
    const int bcol4 = (tid & 1) * 4;
    const int n = bx * 128 + brow;
    const float* wptr = (n < G4) ? (Wf + (size_t)n * E_)
                                 : (Wb + (size_t)(n - G4) * E_);

    unsigned long long acc2[8][4];
    #pragma unroll
    for (int i = 0; i < 8; i++)
        #pragma unroll
        for (int j = 0; j < 4; j++) acc2[i][j] = 0ull;

    for (int k0 = 0; k0 < E_; k0 += 8) {
        float4 a4 = *(const float4*)(aptr + k0 + acol4);
        float4 b4 = *(const float4*)(wptr + k0 + bcol4);
        __syncthreads();
        As[(acol4+0)*128 + arow] = a4.x; As[(acol4+1)*128 + arow] = a4.y;
        As[(acol4+2)*128 + arow] = a4.z; As[(acol4+3)*128 + arow] = a4.w;
        Bs[(bcol4+0)*128 + brow] = b4.x; Bs[(bcol4+1)*128 + brow] = b4.y;
        Bs[(bcol4+2)*128 + brow] = b4.z; Bs[(bcol4+3)*128 + brow] = b4.w;
        __syncthreads();
        #pragma unroll
        for (int k = 0; k < 8; k++) {
            float4 a0 = *(const float4*)&As[k*128 + ty*8];
            float4 a1 = *(const float4*)&As[k*128 + ty*8 + 4];
            ulonglong2 bq0 = *(const ulonglong2*)&Bs[k*128 + tx*8];
            ulonglong2 bq1 = *(const ulonglong2*)&Bs[k*128 + tx*8 + 4];
            float av[8] = {a0.x,a0.y,a0.z,a0.w,a1.x,a1.y,a1.z,a1.w};
            #pragma unroll
            for (int i = 0; i < 8; i++) {
                unsigned long long ap = dup2(av[i]);
                fma2(acc2[i][0], ap, bq0.x);
                fma2(acc2[i][1], ap, bq0.y);
                fma2(acc2[i][2], ap, bq1.x);
                fma2(acc2[i][3], ap, bq1.y);
            }
        }
    }

    __syncthreads();
    #pragma unroll
    for (int i = 0; i < 8; i++) {
        const int ml = ty*8 + i;
        #pragma unroll
        for (int jp = 0; jp < 4; jp++) {
            float lo, hi;
            asm("mov.b64 {%0, %1}, %2;" : "=f"(lo), "=f"(hi) : "l"(acc2[i][jp]));
            tile[ml*129 + tx*8 + jp*2    ] = lo;
            tile[ml*129 + tx*8 + jp*2 + 1] = hi;
        }
    }
    __syncthreads();

    const int d = bx >> 4;
    const int jjbase = bx * 128 - d * G4;
    const float* bias = d ? bb : bf;
    float* outp = g_xwT[d];
    const int wid  = tid >> 5;
    const int lane = tid & 31;
    #pragma unroll 8
    for (int it = 0; it < 64; it++) {
        int group = wid*64 + it;
        int nl = group >> 2;
        int tg = group & 3;
        float v = tile[(tg*32 + lane)*129 + nl] + bias[jjbase + nl];
        outp[((size_t)(by*4 + tg)*G4 + jjbase + nl)*32 + lane] = v;
    }
}

// ---------------- 2) init: h0 -> cur[phase 0], reset flags ------------------
__global__ void init_state(const float* __restrict__ h0)
{
    int i = blockIdx.x * blockDim.x + threadIdx.x;
    if (i < 128) g_flagA[i >> 6][i & 63] = 0;
    if (i < 2*B_*H_) {
        int d = i / (B_*H_);
        int r = i % (B_*H_);
        int b = r / H_, u = r % H_;
        g_cur[d][0][u*32 + b] = h0[i];
    }
}

// ---------------- 3) persistent bidirectional LSTM recurrence ---------------
// 128 blocks x 512 threads. Block = 8 units x 4 gates, one dir.
// warp = (unit-pair p=warp&3, k-quarter kq=warp>>2); lane = batch.
__global__ void __launch_bounds__(512, 1)
lstm_persist(const float* __restrict__ Whhf,
             const float* __restrict__ Whhb,
             const float* __restrict__ c0)
{
    extern __shared__ float sm[];
    float* Wsm = sm;                  // [32][512] rows: g*8 + unit_local
    float* hsm = Wsm + 32*512;        // [32][PITCH] row=batch, col=k (swizzled)
    float* red = hsm + 32*PITCH;      // [12][8][32]

    const int tid  = threadIdx.x;
    const int bid  = blockIdx.x;
    const int warp = tid >> 5;
    const int lane = tid & 31;
    const int d    = bid >> 6;
    const int ub   = (bid & 63) * 8;
    const float* W = d ? Whhb : Whhf;

    for (int i = tid; i < 32*512; i += 512) {
        int rr = i >> 9, k = i & 511;
        int gg = rr >> 3, ii = rr & 7;
        Wsm[rr*512 + k] = W[(size_t)(gg*H_ + ub + ii)*H_ + k];
    }

    const int p  = warp & 3;
    const int kq = warp >> 2;
    const int k0 = kq * 128;
    const int u0 = ub + 2*p;
    const int kx = 8 * (lane & 3);

    float c[2] = {0.f, 0.f};
    if (kq == 0) {
        c[0] = c0[d*(B_*H_) + lane*H_ + u0    ];
        c[1] = c0[d*(B_*H_) + lane*H_ + u0 + 1];
    }
    const float* xwT = g_xwT[d];
    volatile int* flags = g_flagA[d];

    for (int t = 0; t < T_; t++) {
        const int ph  = t & 1;
        const int txw = d ? (T_ - 1 - t) : t;

        // stage h_prev into hsm (coalesced gmem, conflict-free swizzled STS)
        {
            const float* cp = g_cur[d][ph];
            #pragma unroll
            for (int it = 0; it < 8; it++) {
                int q  = tid + it*512;
                int b  = q & 31;
                int uu = (q >> 5) << 2;
                float4 v;
                v.x = __ldcg(cp + (uu+0)*32 + b);
                v.y = __ldcg(cp + (uu+1)*32 + b);
                v.z = __ldcg(cp + (uu+2)*32 + b);
                v.w = __ldcg(cp + (uu+3)*32 + b);
                *(float4*)&hsm[b*PITCH + (uu ^ (8*(b&3)))] = v;
            }
        }

        float xv[8];
        if (kq == 0) {
            const float* bp = xwT + (size_t)txw * G4 * 32 + lane;
            #pragma unroll
            for (int g = 0; g < 4; g++) {
                xv[g*2+0] = __ldcg(bp + (g*H_ + u0    )*32);
                xv[g*2+1] = __ldcg(bp + (g*H_ + u0 + 1)*32);
            }
        }
        __syncthreads();

        unsigned long long acc[8];
        #pragma unroll
        for (int rr = 0; rr < 8; rr++) acc[rr] = 0ull;
        const float* hrow = hsm + lane*PITCH;
        #pragma unroll 8
        for (int q = 0; q < 32; q++) {
            const int k = k0 + q*4;
            ulonglong2 hv = *(const ulonglong2*)&hrow[k ^ kx];
            #pragma unroll
            for (int g = 0; g < 4; g++) {
                ulonglong2 w0 = *(const ulonglong2*)&Wsm[(g*8 + 2*p    )*512 + k];
                ulonglong2 w1 = *(const ulonglong2*)&Wsm[(g*8 + 2*p + 1)*512 + k];
                fma2(acc[g*2+0], w0.x, hv.x); fma2(acc[g*2+0], w0.y, hv.y);
                fma2(acc[g*2+1], w1.x, hv.x); fma2(acc[g*2+1], w1.y, hv.y);
            }
        }
        float av[8];
        #pragma unroll
        for (int rr = 0; rr < 8; rr++) av[rr] = collapse2(acc[rr]);

        if (kq > 0) {
            #pragma unroll
            for (int rr = 0; rr < 8; rr++)
                red[(((kq-1)*4 + p)*8 + rr)*32 + lane] = av[rr];
        }
        __syncthreads();

        if (kq == 0) {
            #pragma unroll
            for (int rr = 0; rr < 8; rr++)
                av[rr] += red[((0*4 + p)*8 + rr)*32 + lane]
                        + red[((1*4 + p)*8 + rr)*32 + lane]
                        + red[((2*4 + p)*8 + rr)*32 + lane];
            #pragma unroll
            for (int e = 0; e < 2; e++) {
                float zi = av[0*2+e] + xv[0*2+e];
                float zf = av[1*2+e] + xv[1*2+e];
                float zg = av[2*2+e] + xv[2*2+e];
                float zo = av[3*2+e] + xv[3*2+e];
                float cn = sigm(zf)*c[e] + sigm(zi)*tanhf(zg);
                float hn = sigm(zo)*tanhf(cn);
                c[e] = cn;
                const int u = u0 + e;
                __stcg(&g_cur[d][ph^1][u*32 + lane], hn);
                __stcg(&g_hT[d][((size_t)txw*H_ + u)*32 + lane], hn);
            }
        }

        __syncthreads();                       // all h writes of this block done
        if (t < T_ - 1) {
            // distributed flag barrier: parallel arrivals, parallel detection
            if (tid == 0) {
                __threadfence();
                flags[bid & 63] = t + 1;
            }
            if (tid < 64) {
                while (flags[tid] <= t) { }
            }
            __syncthreads();
        }
    }
}

// ---------------- 4) output projection feats[b,t,k] -------------------------
// grid = T_ blocks (one t each); warp = batch, lane = k. Coalesced h gather.
__global__ void feats_kernel(const float* __restrict__ Wout,
                             const float* __restrict__ bout)
{
    __shared__ float Ws[32*65];    // [k][jj]
    __shared__ float Rs[64*33];    // [jj][b]

    const int tid = threadIdx.x;
    const int b   = tid >> 5;
    const int k   = tid & 31;
    const int t   = blockIdx.x;

    float acc = 0.0f;

    for (int j0 = 0; j0 < 2*H_; j0 += 64) {
        __syncthreads();
        #pragma unroll
        for (int i = tid; i < 32*64; i += 1024) {
            int kk = i >> 6, jj = i & 63;
            Ws[kk*65 + jj] = Wout[kk * (2*H_) + j0 + jj];
        }
        #pragma unroll
        for (int i = tid; i < 64*32; i += 1024) {
            int jj = i >> 5, bb = i & 31;      // consecutive i -> consecutive bb
            int j = j0 + jj;
            float v = (j < H_)
                ? g_hT[0][((size_t)t*H_ + j      )*32 + bb]
                : g_hT[1][((size_t)t*H_ + (j-H_) )*32 + bb];
            Rs[jj*33 + bb] = v;
        }
        __syncthreads();
        #pragma unroll
        for (int jj = 0; jj < 64; jj++)
            acc += Ws[k*65 + jj] * Rs[jj*33 + b];   // Ws stride-65 CF, Rs bcast
    }
    g_feats[((size_t)b*T_ + t) * K_ + k] = acc + bout[k];
}

// ---------------- 5) Viterbi decode + backtrack ------------------------------
__global__ void viterbi_kernel(const float* __restrict__ trans,
                               float* __restrict__ out, int path_base)
{
    __shared__ float tr[32][33];
    const int tid = threadIdx.x;
    tr[tid >> 5][tid & 31] = trans[tid];
    __syncthreads();

    const int b    = tid >> 5;
    const int lane = tid & 31;

    float v = (lane == 30) ? 0.0f : NEG_;   // START = 30

    for (int t = 0; t < T_; t++) {
        float ft = g_feats[(size_t)(b * T_ + t) * K_ + lane];
        float best = -3.4e38f;
        int   bp   = 0;
        float vcur = v;
        #pragma unroll
        for (int p = 0; p < 32; p++) {
            float vp = __shfl_sync(0xffffffffu, vcur, p);
            float s = vp + tr[lane][p];
            if (s > best) { best = s; bp = p; }
        }
        v = best + ft;
        g_bp[(size_t)(t * 32 + b) * 32 + lane] = (unsigned char)bp;
    }

    float term = v + tr[31][lane];           // STOP = 31

    float bv = term; int bi = lane;
    #pragma unroll
    for (int off = 16; off > 0; off >>= 1) {
        float ov = __shfl_down_sync(0xffffffffu, bv, off);
        int   oi = __shfl_down_sync(0xffffffffu, bi, off);
        if (ov > bv || (ov == bv && oi < bi)) { bv = ov; bi = oi; }
    }
    bi = __shfl_sync(0xffffffffu, bi, 0);
    bv = __shfl_sync(0xffffffffu, bv, 0);

    if (lane == 0) {
        if (path_base > 0) out[b] = bv;
        int tag = bi;
        for (int t = T_ - 1; t >= 0; t--) {
            out[path_base + b * T_ + t] = (float)tag;
            tag = g_bp[(size_t)(t * 32 + b) * 32 + tag];
        }
    }
}

// ---------------- launch -----------------------------------------------------
extern "C" void kernel_launch(void* const* d_in, const int* in_sizes, int n_in,
                              void* d_out, int out_size)
{
    int unit = 0;
    for (int i = 0; i < n_in; i++) {
        if (in_sizes[i] == 12800000) { unit = 1; break; }
        if (in_sizes[i] == 51200000) { unit = 4; break; }
    }

    int i_sent = -1, i_emb = -1, i_bout = -1, i_tr = -1, sent64 = 0;
    int gih[2], nih = 0, ghh[2], nhh = 0, g2i[2], n2 = 0, g3i[3], n3 = 0;
    if (unit) {
        for (int i = 0; i < n_in; i++) {
            const int s = in_sizes[i] / unit;
            if      (s == 8192)     { if (i_sent < 0) { i_sent = i; sent64 = 0; } }
            else if (s == 16384)    { if (i_sent < 0) { i_sent = i; sent64 = 1; } }
            else if (s == 12800000) { if (i_emb  < 0) i_emb  = i; }
            else if (s == 32)       { if (i_bout < 0) i_bout = i; }
            else if (s == 1024)     { if (i_tr   < 0) i_tr   = i; }
            else if (s == 524288)   { if (nih < 2) gih[nih++] = i; }
            else if (s == 1048576)  { if (nhh < 2) ghh[nhh++] = i; }
            else if (s == 2048)     { if (n2  < 2) g2i[n2++]  = i; }
            else if (s == 32768)    { if (n3  < 3) g3i[n3++]  = i; }
        }
    }
    const int out_elems = (unit == 4) ? out_size / 4 : out_size;

    if (!unit || i_sent < 0 || i_emb < 0 || i_bout < 0 || i_tr < 0 ||
        nih != 2 || nhh != 2 || n2 != 2 || n3 != 3) {
        int n = out_size > 0 ? out_size : 1;
        fill_out<<<(n + 255) / 256, 256>>>((float*)d_out, n, 1.0e6f);
        return;
    }

    int I_Wihf, I_Whhf, I_Wihb, I_Whhb, I_bf, I_bb, I_Wout, I_h0, I_c0;
    if (i_sent < i_emb) {   // dict order
        I_Wihf = gih[0]; I_Wihb = gih[1];
        I_Whhf = ghh[0]; I_Whhb = ghh[1];
        I_bf   = g2i[0]; I_bb   = g2i[1];
        I_Wout = g3i[0]; I_h0   = g3i[1]; I_c0 = g3i[2];
    } else {                // name-sorted order
        I_Whhb = ghh[0]; I_Whhf = ghh[1];
        I_Wihb = gih[0]; I_Wihf = gih[1];
        I_bb   = g2i[0]; I_bf   = g2i[1];
        I_Wout = g3i[0]; I_c0   = g3i[1]; I_h0 = g3i[2];
    }

    const void*  sentence = d_in[i_sent];
    const float* emb      = (const float*)d_in[i_emb];
    const float* W_ih_f   = (const float*)d_in[I_Wihf];
    const float* W_hh_f   = (const float*)d_in[I_Whhf];
    const float* b_f      = (const float*)d_in[I_bf];
    const float* W_ih_b   = (const float*)d_in[I_Wihb];
    const float* W_hh_b   = (const float*)d_in[I_Whhb];
    const float* b_b      = (const float*)d_in[I_bb];
    const float* W_out    = (const float*)d_in[I_Wout];
    const float* b_out    = (const float*)d_in[i_bout];
    const float* trans    = (const float*)d_in[i_tr];
    const float* h0       = (const float*)d_in[I_h0];
    const float* c0       = (const float*)d_in[I_c0];
    float* out = (float*)d_out;

    const int path_base = (out_elems >= B_ + B_*T_) ? B_ : 0;

    const int SMEM_G = (2048 + 128*129) * 4;                 // 74240 B
    const int SMEM_P = (32*512 + 32*PITCH + 12*8*32) * 4;    // 143872 B
    cudaFuncSetAttribute(gemm_xw,
                         cudaFuncAttributeMaxDynamicSharedMemorySize, SMEM_G);
    cudaFuncSetAttribute(lstm_persist,
                         cudaFuncAttributeMaxDynamicSharedMemorySize, SMEM_P);

    gemm_xw<<<dim3(32, 64), 256, SMEM_G>>>(sentence, sent64, emb,
                                           W_ih_f, W_ih_b, b_f, b_b);
    init_state<<<64, 512>>>(h0);
    lstm_persist<<<128, 512, SMEM_P>>>(W_hh_f, W_hh_b, c0);
    feats_kernel<<<T_, 1024>>>(W_out, b_out);
    viterbi_kernel<<<1, 1024>>>(trans, out, path_base);
}

// round 10
// speedup vs baseline: 1.3790x; 1.3790x over previous
#include <cuda_runtime.h>
#include <math.h>
#include <stdint.h>

#define B_  32
#define T_  256
#define E_  256            // V,E,H,K = 50000,256,512,32
#define H_  512
#define K_  32
#define V_  50000
#define G4  2048           // 4*H
#define M_  (T_*B_)        // 8192 tokens
#define NEG_ -10000.0f
#define PITCH 516          // hsm row pitch (floats)

// ---------------- scratch (static device globals; no allocation) -------------
__device__ float g_xwT[2][M_*G4];         // [d][(t*2048+n)*32+b]
__device__ float g_hT [2][M_*H_];         // [d][(t*512+u)*32+b]
__device__ float g_cur[2][2][H_*B_];      // [d][phase][u*32+b]
__device__ float g_feats[B_*T_*K_];       // [m][k], m=b*T+t
__device__ unsigned char g_bp[T_*B_*K_];
__device__ int g_cntL1[2][256];           // 4 monotonic counters/dir, 256B stride
__device__ int g_cntL2[2];                // level-2 monotonic counter
__device__ int g_gen2[2];                 // release generation

__device__ __forceinline__ float sigm(float x){ return 1.0f/(1.0f+expf(-x)); }

__device__ __forceinline__ void fma2(unsigned long long &acc,
                                     unsigned long long a, unsigned long long b){
    asm("fma.rn.f32x2 %0, %1, %2, %0;" : "+l"(acc) : "l"(a), "l"(b));
}
__device__ __forceinline__ unsigned long long dup2(float a){
    unsigned long long d;
    asm("mov.b64 %0, {%1, %1};" : "=l"(d) : "f"(a));
    return d;
}
__device__ __forceinline__ float collapse2(unsigned long long v){
    float lo, hi;
    asm("mov.b64 {%0, %1}, %2;" : "=f"(lo), "=f"(hi) : "l"(v));
    return lo + hi;
}

__global__ void fill_out(float* out, int n, float val)
{
    int i = blockIdx.x * blockDim.x + threadIdx.x;
    if (i < n) out[i] = val;
}

// ---------------- 1) embedding-gather + input GEMM + fused transpose --------
__global__ void gemm_xw(const void* __restrict__ sentence, int sent64,
                        const float* __restrict__ emb,
                        const float* __restrict__ Wf,
                        const float* __restrict__ Wb,
                        const float* __restrict__ bf,
                        const float* __restrict__ bb)
{
    extern __shared__ float smg[];
    float* As   = smg;            // [8][128]
    float* Bs   = smg + 1024;     // [8][128]
    float* tile = smg + 2048;     // [128][129]

    const int bx = blockIdx.x;    // 0..31 (N tiles)
    const int by = blockIdx.y;    // 0..63 (M tiles)
    const int tid = threadIdx.x;
    const int tx = tid & 15;
    const int ty = tid >> 4;

    const int arow  = tid >> 1;
    const int acol4 = (tid & 1) * 4;
    const int r  = by * 128 + arow;
    const int tt = r >> 5;
    const int bb_ = r & 31;
    long long w64 = sent64 ? ((const long long*)sentence)[bb_ * T_ + tt]
                           : (long long)((const int*)sentence)[bb_ * T_ + tt];
    unsigned int word = (unsigned int)w64;
    if (word >= V_) word = 0;
    const float* aptr = emb + (size_t)word * E_;

    const int brow  = tid >> 1;
    const int bcol4 = (tid & 1) * 4;
    const int n = bx * 128 + brow;
    const float* wptr = (n < G4) ? (Wf + (size_t)n * E_)
                                 : (Wb + (size_t)(n - G4) * E_);

    unsigned long long acc2[8][4];
    #pragma unroll
    for (int i = 0; i < 8; i++)
        #pragma unroll
        for (int j = 0; j < 4; j++) acc2[i][j] = 0ull;

    for (int k0 = 0; k0 < E_; k0 += 8) {
        float4 a4 = *(const float4*)(aptr + k0 + acol4);
        float4 b4 = *(const float4*)(wptr + k0 + bcol4);
        __syncthreads();
        As[(acol4+0)*128 + arow] = a4.x; As[(acol4+1)*128 + arow] = a4.y;
        As[(acol4+2)*128 + arow] = a4.z; As[(acol4+3)*128 + arow] = a4.w;
        Bs[(bcol4+0)*128 + brow] = b4.x; Bs[(bcol4+1)*128 + brow] = b4.y;
        Bs[(bcol4+2)*128 + brow] = b4.z; Bs[(bcol4+3)*128 + brow] = b4.w;
        __syncthreads();
        #pragma unroll
        for (int k = 0; k < 8; k++) {
            float4 a0 = *(const float4*)&As[k*128 + ty*8];
            float4 a1 = *(const float4*)&As[k*128 + ty*8 + 4];
            ulonglong2 bq0 = *(const ulonglong2*)&Bs[k*128 + tx*8];
            ulonglong2 bq1 = *(const ulonglong2*)&Bs[k*128 + tx*8 + 4];
            float av[8] = {a0.x,a0.y,a0.z,a0.w,a1.x,a1.y,a1.z,a1.w};
            #pragma unroll
            for (int i = 0; i < 8; i++) {
                unsigned long long ap = dup2(av[i]);
                fma2(acc2[i][0], ap, bq0.x);
                fma2(acc2[i][1], ap, bq0.y);
                fma2(acc2[i][2], ap, bq1.x);
                fma2(acc2[i][3], ap, bq1.y);
            }
        }
    }

    __syncthreads();
    #pragma unroll
    for (int i = 0; i < 8; i++) {
        const int ml = ty*8 + i;
        #pragma unroll
        for (int jp = 0; jp < 4; jp++) {
            float lo, hi;
            asm("mov.b64 {%0, %1}, %2;" : "=f"(lo), "=f"(hi) : "l"(acc2[i][jp]));
            tile[ml*129 + tx*8 + jp*2    ] = lo;
            tile[ml*129 + tx*8 + jp*2 + 1] = hi;
        }
    }
    __syncthreads();

    const int d = bx >> 4;
    const int jjbase = bx * 128 - d * G4;
    const float* bias = d ? bb : bf;
    float* outp = g_xwT[d];
    const int wid  = tid >> 5;
    const int lane = tid & 31;
    #pragma unroll 8
    for (int it = 0; it < 64; it++) {
        int group = wid*64 + it;
        int nl = group >> 2;
        int tg = group & 3;
        float v = tile[(tg*32 + lane)*129 + nl] + bias[jjbase + nl];
        outp[((size_t)(by*4 + tg)*G4 + jjbase + nl)*32 + lane] = v;
    }
}

// ---------------- 2) init: h0 -> cur[phase 0], reset barrier state ----------
__global__ void init_state(const float* __restrict__ h0)
{
    int i = blockIdx.x * blockDim.x + threadIdx.x;
    if (i < 512) ((int*)g_cntL1)[i] = 0;
    if (i == 512) {
        g_cntL2[0] = 0; g_cntL2[1] = 0;
        g_gen2[0] = 0;  g_gen2[1] = 0;
    }
    if (i < 2*B_*H_) {
        int d = i / (B_*H_);
        int r = i % (B_*H_);
        int b = r / H_, u = r % H_;
        g_cur[d][0][u*32 + b] = h0[i];
    }
}

// ---------------- 3) persistent bidirectional LSTM recurrence ---------------
// 128 blocks x 512 threads. Block = 8 units x 4 gates, one dir.
// warp = (unit-pair p=warp&3, k-quarter kq=warp>>2); lane = batch.
__global__ void __launch_bounds__(512, 1)
lstm_persist(const float* __restrict__ Whhf,
             const float* __restrict__ Whhb,
             const float* __restrict__ c0)
{
    extern __shared__ float sm[];
    float* Wsm = sm;                  // [32][512] rows: g*8 + unit_local
    float* hsm = Wsm + 32*512;        // [32][PITCH] row=batch, col=k (swizzled)
    float* red = hsm + 32*PITCH;      // [12][8][32]

    const int tid  = threadIdx.x;
    const int bid  = blockIdx.x;
    const int warp = tid >> 5;
    const int lane = tid & 31;
    const int d    = bid >> 6;
    const int ub   = (bid & 63) * 8;
    const float* W = d ? Whhb : Whhf;

    for (int i = tid; i < 32*512; i += 512) {
        int rr = i >> 9, k = i & 511;
        int gg = rr >> 3, ii = rr & 7;
        Wsm[rr*512 + k] = W[(size_t)(gg*H_ + ub + ii)*H_ + k];
    }

    const int p  = warp & 3;
    const int kq = warp >> 2;
    const int k0 = kq * 128;
    const int u0 = ub + 2*p;
    const int kx = 8 * (lane & 3);

    float c[2] = {0.f, 0.f};
    if (kq == 0) {
        c[0] = c0[d*(B_*H_) + lane*H_ + u0    ];
        c[1] = c0[d*(B_*H_) + lane*H_ + u0 + 1];
    }
    const float* xwT = g_xwT[d];
    const int cslot = ((bid & 63) & 3) * 64;   // this block's L1 counter

    for (int t = 0; t < T_; t++) {
        const int ph  = t & 1;
        const int txw = d ? (T_ - 1 - t) : t;

        // stage h_prev into hsm (coalesced gmem, conflict-free swizzled STS)
        {
            const float* cp = g_cur[d][ph];
            #pragma unroll
            for (int it = 0; it < 8; it++) {
                int q  = tid + it*512;
                int b  = q & 31;
                int uu = (q >> 5) << 2;
                float4 v;
                v.x = __ldcg(cp + (uu+0)*32 + b);
                v.y = __ldcg(cp + (uu+1)*32 + b);
                v.z = __ldcg(cp + (uu+2)*32 + b);
                v.w = __ldcg(cp + (uu+3)*32 + b);
                *(float4*)&hsm[b*PITCH + (uu ^ (8*(b&3)))] = v;
            }
        }

        float xv[8];
        if (kq == 0) {
            const float* bp = xwT + (size_t)txw * G4 * 32 + lane;
            #pragma unroll
            for (int g = 0; g < 4; g++) {
                xv[g*2+0] = __ldcg(bp + (g*H_ + u0    )*32);
                xv[g*2+1] = __ldcg(bp + (g*H_ + u0 + 1)*32);
            }
        }
        __syncthreads();

        unsigned long long acc[8];
        #pragma unroll
        for (int rr = 0; rr < 8; rr++) acc[rr] = 0ull;
        const float* hrow = hsm + lane*PITCH;
        #pragma unroll 8
        for (int q = 0; q < 32; q++) {
            const int k = k0 + q*4;
            ulonglong2 hv = *(const ulonglong2*)&hrow[k ^ kx];
            #pragma unroll
            for (int g = 0; g < 4; g++) {
                ulonglong2 w0 = *(const ulonglong2*)&Wsm[(g*8 + 2*p    )*512 + k];
                ulonglong2 w1 = *(const ulonglong2*)&Wsm[(g*8 + 2*p + 1)*512 + k];
                fma2(acc[g*2+0], w0.x, hv.x); fma2(acc[g*2+0], w0.y, hv.y);
                fma2(acc[g*2+1], w1.x, hv.x); fma2(acc[g*2+1], w1.y, hv.y);
            }
        }
        float av[8];
        #pragma unroll
        for (int rr = 0; rr < 8; rr++) av[rr] = collapse2(acc[rr]);

        if (kq > 0) {
            #pragma unroll
            for (int rr = 0; rr < 8; rr++)
                red[(((kq-1)*4 + p)*8 + rr)*32 + lane] = av[rr];
        }
        __syncthreads();

        if (kq == 0) {
            #pragma unroll
            for (int rr = 0; rr < 8; rr++)
                av[rr] += red[((0*4 + p)*8 + rr)*32 + lane]
                        + red[((1*4 + p)*8 + rr)*32 + lane]
                        + red[((2*4 + p)*8 + rr)*32 + lane];
            #pragma unroll
            for (int e = 0; e < 2; e++) {
                float zi = av[0*2+e] + xv[0*2+e];
                float zf = av[1*2+e] + xv[1*2+e];
                float zg = av[2*2+e] + xv[2*2+e];
                float zo = av[3*2+e] + xv[3*2+e];
                float cn = sigm(zf)*c[e] + sigm(zi)*tanhf(zg);
                float hn = sigm(zo)*tanhf(cn);
                c[e] = cn;
                const int u = u0 + e;
                __stcg(&g_cur[d][ph^1][u*32 + lane], hn);
                __stcg(&g_hT[d][((size_t)txw*H_ + u)*32 + lane], hn);
            }
        }

        __syncthreads();                      // all h writes of this block done
        if (t < T_ - 1) {
            // 2-level monotonic-counter barrier (4 L1 counters, 16 arrivals ea)
            if (tid == 0) {
                __threadfence();
                int old = atomicAdd(&g_cntL1[d][cslot], 1);
                if (old == 16*t + 15) {
                    int o2 = atomicAdd(&g_cntL2[d], 1);
                    if (o2 == 4*t + 3) {
                        __threadfence();
                        atomicExch(&g_gen2[d], t + 1);
                    }
                }
                while (*(volatile int*)&g_gen2[d] <= t) { }
                __threadfence();
            }
            __syncthreads();
        }
    }
}

// ---------------- 4) output projection feats[b,t,k] -------------------------
// grid = T_ blocks (one t each); warp = batch, lane = k. Coalesced h gather.
__global__ void feats_kernel(const float* __restrict__ Wout,
                             const float* __restrict__ bout)
{
    __shared__ float Ws[32*65];    // [k][jj]
    __shared__ float Rs[64*33];    // [jj][b]

    const int tid = threadIdx.x;
    const int b   = tid >> 5;
    const int k   = tid & 31;
    const int t   = blockIdx.x;

    float acc = 0.0f;

    for (int j0 = 0; j0 < 2*H_; j0 += 64) {
        __syncthreads();
        #pragma unroll
        for (int i = tid; i < 32*64; i += 1024) {
            int kk = i >> 6, jj = i & 63;
            Ws[kk*65 + jj] = Wout[kk * (2*H_) + j0 + jj];
        }
        #pragma unroll
        for (int i = tid; i < 64*32; i += 1024) {
            int jj = i >> 5, bb = i & 31;
            int j = j0 + jj;
            float v = (j < H_)
                ? g_hT[0][((size_t)t*H_ + j      )*32 + bb]
                : g_hT[1][((size_t)t*H_ + (j-H_) )*32 + bb];
            Rs[jj*33 + bb] = v;
        }
        __syncthreads();
        #pragma unroll
        for (int jj = 0; jj < 64; jj++)
            acc += Ws[k*65 + jj] * Rs[jj*33 + b];
    }
    g_feats[((size_t)b*T_ + t) * K_ + k] = acc + bout[k];
}

// ---------------- 5) Viterbi decode + backtrack ------------------------------
__global__ void viterbi_kernel(const float* __restrict__ trans,
                               float* __restrict__ out, int path_base)
{
    __shared__ float tr[32][33];
    const int tid = threadIdx.x;
    tr[tid >> 5][tid & 31] = trans[tid];
    __syncthreads();

    const int b    = tid >> 5;
    const int lane = tid & 31;

    float v = (lane == 30) ? 0.0f : NEG_;   // START = 30

    for (int t = 0; t < T_; t++) {
        float ft = g_feats[(size_t)(b * T_ + t) * K_ + lane];
        float best = -3.4e38f;
        int   bp   = 0;
        float vcur = v;
        #pragma unroll
        for (int p = 0; p < 32; p++) {
            float vp = __shfl_sync(0xffffffffu, vcur, p);
            float s = vp + tr[lane][p];
            if (s > best) { best = s; bp = p; }
        }
        v = best + ft;
        g_bp[(size_t)(t * 32 + b) * 32 + lane] = (unsigned char)bp;
    }

    float term = v + tr[31][lane];           // STOP = 31

    float bv = term; int bi = lane;
    #pragma unroll
    for (int off = 16; off > 0; off >>= 1) {
        float ov = __shfl_down_sync(0xffffffffu, bv, off);
        int   oi = __shfl_down_sync(0xffffffffu, bi, off);
        if (ov > bv || (ov == bv && oi < bi)) { bv = ov; bi = oi; }
    }
    bi = __shfl_sync(0xffffffffu, bi, 0);
    bv = __shfl_sync(0xffffffffu, bv, 0);

    if (lane == 0) {
        if (path_base > 0) out[b] = bv;
        int tag = bi;
        for (int t = T_ - 1; t >= 0; t--) {
            out[path_base + b * T_ + t] = (float)tag;
            tag = g_bp[(size_t)(t * 32 + b) * 32 + tag];
        }
    }
}

// ---------------- launch -----------------------------------------------------
extern "C" void kernel_launch(void* const* d_in, const int* in_sizes, int n_in,
                              void* d_out, int out_size)
{
    int unit = 0;
    for (int i = 0; i < n_in; i++) {
        if (in_sizes[i] == 12800000) { unit = 1; break; }
        if (in_sizes[i] == 51200000) { unit = 4; break; }
    }

    int i_sent = -1, i_emb = -1, i_bout = -1, i_tr = -1, sent64 = 0;
    int gih[2], nih = 0, ghh[2], nhh = 0, g2i[2], n2 = 0, g3i[3], n3 = 0;
    if (unit) {
        for (int i = 0; i < n_in; i++) {
            const int s = in_sizes[i] / unit;
            if      (s == 8192)     { if (i_sent < 0) { i_sent = i; sent64 = 0; } }
            else if (s == 16384)    { if (i_sent < 0) { i_sent = i; sent64 = 1; } }
            else if (s == 12800000) { if (i_emb  < 0) i_emb  = i; }
            else if (s == 32)       { if (i_bout < 0) i_bout = i; }
            else if (s == 1024)     { if (i_tr   < 0) i_tr   = i; }
            else if (s == 524288)   { if (nih < 2) gih[nih++] = i; }
            else if (s == 1048576)  { if (nhh < 2) ghh[nhh++] = i; }
            else if (s == 2048)     { if (n2  < 2) g2i[n2++]  = i; }
            else if (s == 32768)    { if (n3  < 3) g3i[n3++]  = i; }
        }
    }
    const int out_elems = (unit == 4) ? out_size / 4 : out_size;

    if (!unit || i_sent < 0 || i_emb < 0 || i_bout < 0 || i_tr < 0 ||
        nih != 2 || nhh != 2 || n2 != 2 || n3 != 3) {
        int n = out_size > 0 ? out_size : 1;
        fill_out<<<(n + 255) / 256, 256>>>((float*)d_out, n, 1.0e6f);
        return;
    }

    int I_Wihf, I_Whhf, I_Wihb, I_Whhb, I_bf, I_bb, I_Wout, I_h0, I_c0;
    if (i_sent < i_emb) {   // dict order
        I_Wihf = gih[0]; I_Wihb = gih[1];
        I_Whhf = ghh[0]; I_Whhb = ghh[1];
        I_bf   = g2i[0]; I_bb   = g2i[1];
        I_Wout = g3i[0]; I_h0   = g3i[1]; I_c0 = g3i[2];
    } else {                // name-sorted order
        I_Whhb = ghh[0]; I_Whhf = ghh[1];
        I_Wihb = gih[0]; I_Wihf = gih[1];
        I_bb   = g2i[0]; I_bf   = g2i[1];
        I_Wout = g3i[0]; I_c0   = g3i[1]; I_h0 = g3i[2];
    }

    const void*  sentence = d_in[i_sent];
    const float* emb      = (const float*)d_in[i_emb];
    const float* W_ih_f   = (const float*)d_in[I_Wihf];
    const float* W_hh_f   = (const float*)d_in[I_Whhf];
    const float* b_f      = (const float*)d_in[I_bf];
    const float* W_ih_b   = (const float*)d_in[I_Wihb];
    const float* W_hh_b   = (const float*)d_in[I_Whhb];
    const float* b_b      = (const float*)d_in[I_bb];
    const float* W_out    = (const float*)d_in[I_Wout];
    const float* b_out    = (const float*)d_in[i_bout];
    const float* trans    = (const float*)d_in[i_tr];
    const float* h0       = (const float*)d_in[I_h0];
    const float* c0       = (const float*)d_in[I_c0];
    float* out = (float*)d_out;

    const int path_base = (out_elems >= B_ + B_*T_) ? B_ : 0;

    const int SMEM_G = (2048 + 128*129) * 4;                 // 74240 B
    const int SMEM_P = (32*512 + 32*PITCH + 12*8*32) * 4;    // 143872 B
    cudaFuncSetAttribute(gemm_xw,
                         cudaFuncAttributeMaxDynamicSharedMemorySize, SMEM_G);
    cudaFuncSetAttribute(lstm_persist,
                         cudaFuncAttributeMaxDynamicSharedMemorySize, SMEM_P);

    gemm_xw<<<dim3(32, 64), 256, SMEM_G>>>(sentence, sent64, emb,
                                           W_ih_f, W_ih_b, b_f, b_b);
    init_state<<<64, 512>>>(h0);
    lstm_persist<<<128, 512, SMEM_P>>>(W_hh_f, W_hh_b, c0);
    feats_kernel<<<T_, 1024>>>(W_out, b_out);
    viterbi_kernel<<<1, 1024>>>(trans, out, path_base);
}

// round 11
// speedup vs baseline: 1.4203x; 1.0300x over previous
#include <cuda_runtime.h>
#include <math.h>
#include <stdint.h>

#define B_  32
#define T_  256
#define E_  256            // V,E,H,K = 50000,256,512,32
#define H_  512
#define K_  32
#define V_  50000
#define G4  2048           // 4*H
#define M_  (T_*B_)        // 8192 tokens
#define NEG_ -10000.0f
#define PITCH 516          // hsm row pitch (floats), 516*4B divisible by 16

// ---------------- scratch (static device globals; no allocation) -------------
__device__ float g_xwT[2][M_*G4];         // [d][(t*2048+n)*32+b]
__device__ float g_hT [2][M_*H_];         // [d][(t*512+u)*32+b]  archive (feats)
__device__ float g_cur[2][2][B_*H_];      // [d][phase][b*512+u]  b-MAJOR state
__device__ float g_feats[B_*T_*K_];       // [m][k], m=b*T+t
__device__ unsigned char g_bp[T_*B_*K_];
__device__ int g_cnt2[2];                 // central barrier (R8-proven)
__device__ int g_gen2[2];

__device__ __forceinline__ float sigm(float x){ return 1.0f/(1.0f+expf(-x)); }

__device__ __forceinline__ void fma2(unsigned long long &acc,
                                     unsigned long long a, unsigned long long b){
    asm("fma.rn.f32x2 %0, %1, %2, %0;" : "+l"(acc) : "l"(a), "l"(b));
}
__device__ __forceinline__ unsigned long long dup2(float a){
    unsigned long long d;
    asm("mov.b64 %0, {%1, %1};" : "=l"(d) : "f"(a));
    return d;
}
__device__ __forceinline__ float collapse2(unsigned long long v){
    float lo, hi;
    asm("mov.b64 {%0, %1}, %2;" : "=f"(lo), "=f"(hi) : "l"(v));
    return lo + hi;
}

__global__ void fill_out(float* out, int n, float val)
{
    int i = blockIdx.x * blockDim.x + threadIdx.x;
    if (i < n) out[i] = val;
}

// ---------------- 1) embedding-gather + input GEMM + fused transpose --------
__global__ void gemm_xw(const void* __restrict__ sentence, int sent64,
                        const float* __restrict__ emb,
                        const float* __restrict__ Wf,
                        const float* __restrict__ Wb,
                        const float* __restrict__ bf,
                        const float* __restrict__ bb)
{
    extern __shared__ float smg[];
    float* As   = smg;            // [8][128]
    float* Bs   = smg + 1024;     // [8][128]
    float* tile = smg + 2048;     // [128][129]

    const int bx = blockIdx.x;    // 0..31 (N tiles)
    const int by = blockIdx.y;    // 0..63 (M tiles)
    const int tid = threadIdx.x;
    const int tx = tid & 15;
    const int ty = tid >> 4;

    const int arow  = tid >> 1;
    const int acol4 = (tid & 1) * 4;
    const int r  = by * 128 + arow;
    const int tt = r >> 5;
    const int bb_ = r & 31;
    long long w64 = sent64 ? ((const long long*)sentence)[bb_ * T_ + tt]
                           : (long long)((const int*)sentence)[bb_ * T_ + tt];
    unsigned int word = (unsigned int)w64;
    if (word >= V_) word = 0;
    const float* aptr = emb + (size_t)word * E_;

    const int brow  = tid >> 1;
    const int bcol4 = (tid & 1) * 4;
    const int n = bx * 128 + brow;
    const float* wptr = (n < G4) ? (Wf + (size_t)n * E_)
                                 : (Wb + (size_t)(n - G4) * E_);

    unsigned long long acc2[8][4];
    #pragma unroll
    for (int i = 0; i < 8; i++)
        #pragma unroll
        for (int j = 0; j < 4; j++) acc2[i][j] = 0ull;

    for (int k0 = 0; k0 < E_; k0 += 8) {
        float4 a4 = *(const float4*)(aptr + k0 + acol4);
        float4 b4 = *(const float4*)(wptr + k0 + bcol4);
        __syncthreads();
        As[(acol4+0)*128 + arow] = a4.x; As[(acol4+1)*128 + arow] = a4.y;
        As[(acol4+2)*128 + arow] = a4.z; As[(acol4+3)*128 + arow] = a4.w;
        Bs[(bcol4+0)*128 + brow] = b4.x; Bs[(bcol4+1)*128 + brow] = b4.y;
        Bs[(bcol4+2)*128 + brow] = b4.z; Bs[(bcol4+3)*128 + brow] = b4.w;
        __syncthreads();
        #pragma unroll
        for (int k = 0; k < 8; k++) {
            float4 a0 = *(const float4*)&As[k*128 + ty*8];
            float4 a1 = *(const float4*)&As[k*128 + ty*8 + 4];
            ulonglong2 bq0 = *(const ulonglong2*)&Bs[k*128 + tx*8];
            ulonglong2 bq1 = *(const ulonglong2*)&Bs[k*128 + tx*8 + 4];
            float av[8] = {a0.x,a0.y,a0.z,a0.w,a1.x,a1.y,a1.z,a1.w};
            #pragma unroll
            for (int i = 0; i < 8; i++) {
                unsigned long long ap = dup2(av[i]);
                fma2(acc2[i][0], ap, bq0.x);
                fma2(acc2[i][1], ap, bq0.y);
                fma2(acc2[i][2], ap, bq1.x);
                fma2(acc2[i][3], ap, bq1.y);
            }
        }
    }

    __syncthreads();
    #pragma unroll
    for (int i = 0; i < 8; i++) {
        const int ml = ty*8 + i;
        #pragma unroll
        for (int jp = 0; jp < 4; jp++) {
            float lo, hi;
            asm("mov.b64 {%0, %1}, %2;" : "=f"(lo), "=f"(hi) : "l"(acc2[i][jp]));
            tile[ml*129 + tx*8 + jp*2    ] = lo;
            tile[ml*129 + tx*8 + jp*2 + 1] = hi;
        }
    }
    __syncthreads();

    const int d = bx >> 4;
    const int jjbase = bx * 128 - d * G4;
    const float* bias = d ? bb : bf;
    float* outp = g_xwT[d];
    const int wid  = tid >> 5;
    const int lane = tid & 31;
    #pragma unroll 8
    for (int it = 0; it < 64; it++) {
        int group = wid*64 + it;
        int nl = group >> 2;
        int tg = group & 3;
        float v = tile[(tg*32 + lane)*129 + nl] + bias[jjbase + nl];
        outp[((size_t)(by*4 + tg)*G4 + jjbase + nl)*32 + lane] = v;
    }
}

// ---------------- 2) init: h0 -> cur[phase 0] (identity copy), barrier ------
__global__ void init_state(const float* __restrict__ h0)
{
    int i = blockIdx.x * blockDim.x + threadIdx.x;
    if (i == 0) { g_cnt2[0] = 0; g_cnt2[1] = 0; g_gen2[0] = 0; g_gen2[1] = 0; }
    if (i < 2*B_*H_) {
        int d = i / (B_*H_);
        // h0 is [d][b][u]; g_cur[d][0] is [b*512+u] -> identity
        g_cur[d][0][i - d*(B_*H_)] = h0[i];
    }
}

// ---------------- 3) persistent bidirectional LSTM recurrence ---------------
// 128 blocks x 512 threads. Block = 8 units x 4 gates, one dir.
// warp = (unit-pair p=warp&3, k-quarter kq=warp>>2); lane = batch.
__global__ void __launch_bounds__(512, 1)
lstm_persist(const float* __restrict__ Whhf,
             const float* __restrict__ Whhb,
             const float* __restrict__ c0)
{
    extern __shared__ float sm[];
    float* Wsm = sm;                  // [32][512] rows: g*8 + unit_local
    float* hsm = Wsm + 32*512;        // [32][PITCH] row=batch, col=k (swizzled)
    float* red = hsm + 32*PITCH;      // [12][8][32]

    const int tid  = threadIdx.x;
    const int bid  = blockIdx.x;
    const int warp = tid >> 5;
    const int lane = tid & 31;
    const int d    = bid >> 6;
    const int ub   = (bid & 63) * 8;
    const float* W = d ? Whhb : Whhf;

    for (int i = tid; i < 32*512; i += 512) {
        int rr = i >> 9, k = i & 511;
        int gg = rr >> 3, ii = rr & 7;
        Wsm[rr*512 + k] = W[(size_t)(gg*H_ + ub + ii)*H_ + k];
    }

    const int p  = warp & 3;
    const int kq = warp >> 2;
    const int k0 = kq * 128;
    const int u0 = ub + 2*p;
    const int kx = 8 * (lane & 3);

    float c[2] = {0.f, 0.f};
    if (kq == 0) {
        c[0] = c0[d*(B_*H_) + lane*H_ + u0    ];
        c[1] = c0[d*(B_*H_) + lane*H_ + u0 + 1];
    }
    const float* xwT = g_xwT[d];

    // stage precompute: thread -> (b, uq) for the vectorized h stage
    const int sb  = tid >> 4;          // 0..31  batch row (per iter offset +0)
    const int suq = (tid & 15);        // quad idx base; iter adds 16

    for (int t = 0; t < T_; t++) {
        const int ph  = t & 1;
        const int txw = d ? (T_ - 1 - t) : t;

        // stage h_prev: b-major g_cur -> LDG.128 + conflict-free STS.128
        // 4096 quads: thread handles (b = tid>>4, uq = (tid&15) + 16*it)
        {
            const float* cp = g_cur[d][ph];
            const int kxb = 8 * (sb & 3);     // swizzle for row sb
            #pragma unroll
            for (int it = 0; it < 8; it++) {
                int uq = suq + it*16;          // 0..127
                float4 v = *(const float4*)__builtin_assume_aligned(
                               (const void*)(cp + sb*H_ + uq*4), 16);
                *(float4*)&hsm[sb*PITCH + ((uq*4) ^ kxb)] = v;
            }
        }

        float xv[8];
        if (kq == 0) {
            const float* bp = xwT + (size_t)txw * G4 * 32 + lane;
            #pragma unroll
            for (int g = 0; g < 4; g++) {
                xv[g*2+0] = __ldcg(bp + (g*H_ + u0    )*32);
                xv[g*2+1] = __ldcg(bp + (g*H_ + u0 + 1)*32);
            }
        }
        __syncthreads();

        unsigned long long acc[8];
        #pragma unroll
        for (int rr = 0; rr < 8; rr++) acc[rr] = 0ull;
        const float* hrow = hsm + lane*PITCH;
        #pragma unroll 8
        for (int q = 0; q < 32; q++) {
            const int k = k0 + q*4;
            ulonglong2 hv = *(const ulonglong2*)&hrow[k ^ kx];
            #pragma unroll
            for (int g = 0; g < 4; g++) {
                ulonglong2 w0 = *(const ulonglong2*)&Wsm[(g*8 + 2*p    )*512 + k];
                ulonglong2 w1 = *(const ulonglong2*)&Wsm[(g*8 + 2*p + 1)*512 + k];
                fma2(acc[g*2+0], w0.x, hv.x); fma2(acc[g*2+0], w0.y, hv.y);
                fma2(acc[g*2+1], w1.x, hv.x); fma2(acc[g*2+1], w1.y, hv.y);
            }
        }
        float av[8];
        #pragma unroll
        for (int rr = 0; rr < 8; rr++) av[rr] = collapse2(acc[rr]);

        if (kq > 0) {
            #pragma unroll
            for (int rr = 0; rr < 8; rr++)
                red[(((kq-1)*4 + p)*8 + rr)*32 + lane] = av[rr];
        }
        __syncthreads();

        if (kq == 0) {
            #pragma unroll
            for (int rr = 0; rr < 8; rr++)
                av[rr] += red[((0*4 + p)*8 + rr)*32 + lane]
                        + red[((1*4 + p)*8 + rr)*32 + lane]
                        + red[((2*4 + p)*8 + rr)*32 + lane];
            #pragma unroll
            for (int e = 0; e < 2; e++) {
                float zi = av[0*2+e] + xv[0*2+e];
                float zf = av[1*2+e] + xv[1*2+e];
                float zg = av[2*2+e] + xv[2*2+e];
                float zo = av[3*2+e] + xv[3*2+e];
                float cn = sigm(zf)*c[e] + sigm(zi)*tanhf(zg);
                float hn = sigm(zo)*tanhf(cn);
                c[e] = cn;
                const int u = u0 + e;
                __stcg(&g_cur[d][ph^1][lane*H_ + u], hn);                // b-major state
                __stcg(&g_hT[d][((size_t)txw*H_ + u)*32 + lane], hn);    // archive
            }
        }

        __syncthreads();                      // all h writes of this block done
        if (t < T_ - 1) {
            // R8-proven central-atomic barrier (per direction, 64 arrivals)
            if (tid == 0) {
                __threadfence();
                int a = atomicAdd(&g_cnt2[d], 1);
                if (a == 63) {
                    atomicExch(&g_cnt2[d], 0);
                    __threadfence();
                    atomicExch(&g_gen2[d], t + 1);
                } else {
                    while (*(volatile int*)&g_gen2[d] <= t) { }
                }
                __threadfence();
            }
            __syncthreads();
        }
    }
}

// ---------------- 4) output projection feats[b,t,k] -------------------------
// grid = T_ blocks; warp = batch, lane = k. Coalesced h gather (87us proven).
__global__ void feats_kernel(const float* __restrict__ Wout,
                             const float* __restrict__ bout)
{
    __shared__ float Ws[32*65];    // [k][jj]
    __shared__ float Rs[64*33];    // [jj][b]

    const int tid = threadIdx.x;
    const int b   = tid >> 5;
    const int k   = tid & 31;
    const int t   = blockIdx.x;

    float acc = 0.0f;

    for (int j0 = 0; j0 < 2*H_; j0 += 64) {
        __syncthreads();
        #pragma unroll
        for (int i = tid; i < 32*64; i += 1024) {
            int kk = i >> 6, jj = i & 63;
            Ws[kk*65 + jj] = Wout[kk * (2*H_) + j0 + jj];
        }
        #pragma unroll
        for (int i = tid; i < 64*32; i += 1024) {
            int jj = i >> 5, bb = i & 31;
            int j = j0 + jj;
            float v = (j < H_)
                ? g_hT[0][((size_t)t*H_ + j      )*32 + bb]
                : g_hT[1][((size_t)t*H_ + (j-H_) )*32 + bb];
            Rs[jj*33 + bb] = v;
        }
        __syncthreads();
        #pragma unroll
        for (int jj = 0; jj < 64; jj++)
            acc += Ws[k*65 + jj] * Rs[jj*33 + b];
    }
    g_feats[((size_t)b*T_ + t) * K_ + k] = acc + bout[k];
}

// ---------------- 5) Viterbi decode + backtrack ------------------------------
__global__ void viterbi_kernel(const float* __restrict__ trans,
                               float* __restrict__ out, int path_base)
{
    __shared__ float tr[32][33];
    const int tid = threadIdx.x;
    tr[tid >> 5][tid & 31] = trans[tid];
    __syncthreads();

    const int b    = tid >> 5;
    const int lane = tid & 31;

    float v = (lane == 30) ? 0.0f : NEG_;   // START = 30

    for (int t = 0; t < T_; t++) {
        float ft = g_feats[(size_t)(b * T_ + t) * K_ + lane];
        float best = -3.4e38f;
        int   bp   = 0;
        float vcur = v;
        #pragma unroll
        for (int p = 0; p < 32; p++) {
            float vp = __shfl_sync(0xffffffffu, vcur, p);
            float s = vp + tr[lane][p];
            if (s > best) { best = s; bp = p; }
        }
        v = best + ft;
        g_bp[(size_t)(t * 32 + b) * 32 + lane] = (unsigned char)bp;
    }

    float term = v + tr[31][lane];           // STOP = 31

    float bv = term; int bi = lane;
    #pragma unroll
    for (int off = 16; off > 0; off >>= 1) {
        float ov = __shfl_down_sync(0xffffffffu, bv, off);
        int   oi = __shfl_down_sync(0xffffffffu, bi, off);
        if (ov > bv || (ov == bv && oi < bi)) { bv = ov; bi = oi; }
    }
    bi = __shfl_sync(0xffffffffu, bi, 0);
    bv = __shfl_sync(0xffffffffu, bv, 0);

    if (lane == 0) {
        if (path_base > 0) out[b] = bv;
        int tag = bi;
        for (int t = T_ - 1; t >= 0; t--) {
            out[path_base + b * T_ + t] = (float)tag;
            tag = g_bp[(size_t)(t * 32 + b) * 32 + tag];
        }
    }
}

// ---------------- launch -----------------------------------------------------
extern "C" void kernel_launch(void* const* d_in, const int* in_sizes, int n_in,
                              void* d_out, int out_size)
{
    int unit = 0;
    for (int i = 0; i < n_in; i++) {
        if (in_sizes[i] == 12800000) { unit = 1; break; }
        if (in_sizes[i] == 51200000) { unit = 4; break; }
    }

    int i_sent = -1, i_emb = -1, i_bout = -1, i_tr = -1, sent64 = 0;
    int gih[2], nih = 0, ghh[2], nhh = 0, g2i[2], n2 = 0, g3i[3], n3 = 0;
    if (unit) {
        for (int i = 0; i < n_in; i++) {
            const int s = in_sizes[i] / unit;
            if      (s == 8192)     { if (i_sent < 0) { i_sent = i; sent64 = 0; } }
            else if (s == 16384)    { if (i_sent < 0) { i_sent = i; sent64 = 1; } }
            else if (s == 12800000) { if (i_emb  < 0) i_emb  = i; }
            else if (s == 32)       { if (i_bout < 0) i_bout = i; }
            else if (s == 1024)     { if (i_tr   < 0) i_tr   = i; }
            else if (s == 524288)   { if (nih < 2) gih[nih++] = i; }
            else if (s == 1048576)  { if (nhh < 2) ghh[nhh++] = i; }
            else if (s == 2048)     { if (n2  < 2) g2i[n2++]  = i; }
            else if (s == 32768)    { if (n3  < 3) g3i[n3++]  = i; }
        }
    }
    const int out_elems = (unit == 4) ? out_size / 4 : out_size;

    if (!unit || i_sent < 0 || i_emb < 0 || i_bout < 0 || i_tr < 0 ||
        nih != 2 || nhh != 2 || n2 != 2 || n3 != 3) {
        int n = out_size > 0 ? out_size : 1;
        fill_out<<<(n + 255) / 256, 256>>>((float*)d_out, n, 1.0e6f);
        return;
    }

    int I_Wihf, I_Whhf, I_Wihb, I_Whhb, I_bf, I_bb, I_Wout, I_h0, I_c0;
    if (i_sent < i_emb) {   // dict order
        I_Wihf = gih[0]; I_Wihb = gih[1];
        I_Whhf = ghh[0]; I_Whhb = ghh[1];
        I_bf   = g2i[0]; I_bb   = g2i[1];
        I_Wout = g3i[0]; I_h0   = g3i[1]; I_c0 = g3i[2];
    } else {                // name-sorted order
        I_Whhb = ghh[0]; I_Whhf = ghh[1];
        I_Wihb = gih[0]; I_Wihf = gih[1];
        I_bb   = g2i[0]; I_bf   = g2i[1];
        I_Wout = g3i[0]; I_c0   = g3i[1]; I_h0 = g3i[2];
    }

    const void*  sentence = d_in[i_sent];
    const float* emb      = (const float*)d_in[i_emb];
    const float* W_ih_f   = (const float*)d_in[I_Wihf];
    const float* W_hh_f   = (const float*)d_in[I_Whhf];
    const float* b_f      = (const float*)d_in[I_bf];
    const float* W_ih_b   = (const float*)d_in[I_Wihb];
    const float* W_hh_b   = (const float*)d_in[I_Whhb];
    const float* b_b      = (const float*)d_in[I_bb];
    const float* W_out    = (const float*)d_in[I_Wout];
    const float* b_out    = (const float*)d_in[i_bout];
    const float* trans    = (const float*)d_in[i_tr];
    const float* h0       = (const float*)d_in[I_h0];
    const float* c0       = (const float*)d_in[I_c0];
    float* out = (float*)d_out;

    const int path_base = (out_elems >= B_ + B_*T_) ? B_ : 0;

    const int SMEM_G = (2048 + 128*129) * 4;                 // 74240 B
    const int SMEM_P = (32*512 + 32*PITCH + 12*8*32) * 4;    // 143872 B
    cudaFuncSetAttribute(gemm_xw,
                         cudaFuncAttributeMaxDynamicSharedMemorySize, SMEM_G);
    cudaFuncSetAttribute(lstm_persist,
                         cudaFuncAttributeMaxDynamicSharedMemorySize, SMEM_P);

    gemm_xw<<<dim3(32, 64), 256, SMEM_G>>>(sentence, sent64, emb,
                                           W_ih_f, W_ih_b, b_f, b_b);
    init_state<<<64, 512>>>(h0);
    lstm_persist<<<128, 512, SMEM_P>>>(W_hh_f, W_hh_b, c0);
    feats_kernel<<<T_, 1024>>>(W_out, b_out);
    viterbi_kernel<<<1, 1024>>>(trans, out, path_base);
}

// round 12
// speedup vs baseline: 1.4206x; 1.0002x over previous
#include <cuda_runtime.h>
#include <math.h>
#include <stdint.h>

#define B_  32
#define T_  256
#define E_  256            // V,E,H,K = 50000,256,512,32
#define H_  512
#define K_  32
#define V_  50000
#define G4  2048           // 4*H
#define M_  (T_*B_)        // 8192 tokens
#define NEG_ -10000.0f
#define PITCH 516          // hsm row pitch (floats)

// ---------------- scratch (static device globals; no allocation) -------------
__device__ float g_xwT[2][M_*G4];         // [d][(t*2048+n)*32+b]
__device__ float g_hT [2][M_*H_];         // [d][(t*512+u)*32+b]  archive (feats)
__device__ float g_cur[2][2][B_*H_];      // [d][phase][b*512+u]  b-major state
__device__ float g_feats[B_*T_*K_];       // [m][k], m=b*T+t
__device__ unsigned char g_bp[T_*B_*K_];
__device__ int g_cnt2[2];                 // monotonic arrival counters
__device__ int g_gen2[2];                 // release generations

__device__ __forceinline__ float sigm(float x){ return 1.0f/(1.0f+expf(-x)); }

__device__ __forceinline__ void fma2(unsigned long long &acc,
                                     unsigned long long a, unsigned long long b){
    asm("fma.rn.f32x2 %0, %1, %2, %0;" : "+l"(acc) : "l"(a), "l"(b));
}
__device__ __forceinline__ unsigned long long dup2(float a){
    unsigned long long d;
    asm("mov.b64 %0, {%1, %1};" : "=l"(d) : "f"(a));
    return d;
}
__device__ __forceinline__ float collapse2(unsigned long long v){
    float lo, hi;
    asm("mov.b64 {%0, %1}, %2;" : "=f"(lo), "=f"(hi) : "l"(v));
    return lo + hi;
}
__device__ __forceinline__ int atom_add_acqrel(int* a, int v){
    int old;
    asm volatile("atom.add.acq_rel.gpu.global.s32 %0, [%1], %2;"
                 : "=r"(old) : "l"(a), "r"(v) : "memory");
    return old;
}
__device__ __forceinline__ int ld_acquire(int* a){
    int v;
    asm volatile("ld.acquire.gpu.global.s32 %0, [%1];"
                 : "=r"(v) : "l"(a) : "memory");
    return v;
}
__device__ __forceinline__ void st_release(int* a, int v){
    asm volatile("st.release.gpu.global.s32 [%0], %1;"
                 :: "l"(a), "r"(v) : "memory");
}

__global__ void fill_out(float* out, int n, float val)
{
    int i = blockIdx.x * blockDim.x + threadIdx.x;
    if (i < n) out[i] = val;
}

// ---------------- 1) embedding-gather + input GEMM + fused transpose --------
__global__ void gemm_xw(const void* __restrict__ sentence, int sent64,
                        const float* __restrict__ emb,
                        const float* __restrict__ Wf,
                        const float* __restrict__ Wb,
                        const float* __restrict__ bf,
                        const float* __restrict__ bb)
{
    extern __shared__ float smg[];
    float* As   = smg;            // [8][128]
    float* Bs   = smg + 1024;     // [8][128]
    float* tile = smg + 2048;     // [128][129]

    const int bx = blockIdx.x;    // 0..31 (N tiles)
    const int by = blockIdx.y;    // 0..63 (M tiles)
    const int tid = threadIdx.x;
    const int tx = tid & 15;
    const int ty = tid >> 4;

    const int arow  = tid >> 1;
    const int acol4 = (tid & 1) * 4;
    const int r  = by * 128 + arow;
    const int tt = r >> 5;
    const int bb_ = r & 31;
    long long w64 = sent64 ? ((const long long*)sentence)[bb_ * T_ + tt]
                           : (long long)((const int*)sentence)[bb_ * T_ + tt];
    unsigned int word = (unsigned int)w64;
    if (word >= V_) word = 0;
    const float* aptr = emb + (size_t)word * E_;

    const int brow  = tid >> 1;
    const int bcol4 = (tid & 1) * 4;
    const int n = bx * 128 + brow;
    const float* wptr = (n < G4) ? (Wf + (size_t)n * E_)
                                 : (Wb + (size_t)(n - G4) * E_);

    unsigned long long acc2[8][4];
    #pragma unroll
    for (int i = 0; i < 8; i++)
        #pragma unroll
        for (int j = 0; j < 4; j++) acc2[i][j] = 0ull;

    for (int k0 = 0; k0 < E_; k0 += 8) {
        float4 a4 = *(const float4*)(aptr + k0 + acol4);
        float4 b4 = *(const float4*)(wptr + k0 + bcol4);
        __syncthreads();
        As[(acol4+0)*128 + arow] = a4.x; As[(acol4+1)*128 + arow] = a4.y;
        As[(acol4+2)*128 + arow] = a4.z; As[(acol4+3)*128 + arow] = a4.w;
        Bs[(bcol4+0)*128 + brow] = b4.x; Bs[(bcol4+1)*128 + brow] = b4.y;
        Bs[(bcol4+2)*128 + brow] = b4.z; Bs[(bcol4+3)*128 + brow] = b4.w;
        __syncthreads();
        #pragma unroll
        for (int k = 0; k < 8; k++) {
            float4 a0 = *(const float4*)&As[k*128 + ty*8];
            float4 a1 = *(const float4*)&As[k*128 + ty*8 + 4];
            ulonglong2 bq0 = *(const ulonglong2*)&Bs[k*128 + tx*8];
            ulonglong2 bq1 = *(const ulonglong2*)&Bs[k*128 + tx*8 + 4];
            float av[8] = {a0.x,a0.y,a0.z,a0.w,a1.x,a1.y,a1.z,a1.w};
            #pragma unroll
            for (int i = 0; i < 8; i++) {
                unsigned long long ap = dup2(av[i]);
                fma2(acc2[i][0], ap, bq0.x);
                fma2(acc2[i][1], ap, bq0.y);
                fma2(acc2[i][2], ap, bq1.x);
                fma2(acc2[i][3], ap, bq1.y);
            }
        }
    }

    __syncthreads();
    #pragma unroll
    for (int i = 0; i < 8; i++) {
        const int ml = ty*8 + i;
        #pragma unroll
        for (int jp = 0; jp < 4; jp++) {
            float lo, hi;
            asm("mov.b64 {%0, %1}, %2;" : "=f"(lo), "=f"(hi) : "l"(acc2[i][jp]));
            tile[ml*129 + tx*8 + jp*2    ] = lo;
            tile[ml*129 + tx*8 + jp*2 + 1] = hi;
        }
    }
    __syncthreads();

    const int d = bx >> 4;
    const int jjbase = bx * 128 - d * G4;
    const float* bias = d ? bb : bf;
    float* outp = g_xwT[d];
    const int wid  = tid >> 5;
    const int lane = tid & 31;
    #pragma unroll 8
    for (int it = 0; it < 64; it++) {
        int group = wid*64 + it;
        int nl = group >> 2;
        int tg = group & 3;
        float v = tile[(tg*32 + lane)*129 + nl] + bias[jjbase + nl];
        outp[((size_t)(by*4 + tg)*G4 + jjbase + nl)*32 + lane] = v;
    }
}

// ---------------- 2) init: h0 -> cur[phase 0] (identity copy), barrier ------
__global__ void init_state(const float* __restrict__ h0)
{
    int i = blockIdx.x * blockDim.x + threadIdx.x;
    if (i == 0) { g_cnt2[0] = 0; g_cnt2[1] = 0; g_gen2[0] = 0; g_gen2[1] = 0; }
    if (i < 2*B_*H_) {
        int d = i / (B_*H_);
        g_cur[d][0][i - d*(B_*H_)] = h0[i];
    }
}

// ---------------- 3) persistent bidirectional LSTM recurrence ---------------
// 128 blocks x 1024 threads (32 warps). Block = 8 units x 4 gates, one dir.
// warp = (unit-pair p=warp&3, k-eighth kq=warp>>2); lane = batch.
__global__ void __launch_bounds__(1024, 1)
lstm_persist(const float* __restrict__ Whhf,
             const float* __restrict__ Whhb,
             const float* __restrict__ c0)
{
    extern __shared__ float sm[];
    float* Wsm = sm;                  // [32][512] rows: g*8 + unit_local
    float* hsm = Wsm + 32*512;        // [32][PITCH] row=batch, col=k (swizzled)
    float* red = hsm + 32*PITCH;      // [28][8][32] k-partials (kq=1..7)

    const int tid  = threadIdx.x;
    const int bid  = blockIdx.x;
    const int warp = tid >> 5;
    const int lane = tid & 31;
    const int d    = bid >> 6;
    const int ub   = (bid & 63) * 8;
    const float* W = d ? Whhb : Whhf;

    for (int i = tid; i < 32*512; i += 1024) {
        int rr = i >> 9, k = i & 511;
        int gg = rr >> 3, ii = rr & 7;
        Wsm[rr*512 + k] = W[(size_t)(gg*H_ + ub + ii)*H_ + k];
    }

    const int p  = warp & 3;          // unit pair
    const int kq = warp >> 2;         // k eighth (0..7)
    const int k0 = kq * 64;
    const int u0 = ub + 2*p;
    const int kx = 8 * (lane & 3);

    float c[2] = {0.f, 0.f};
    if (kq == 0) {
        c[0] = c0[d*(B_*H_) + lane*H_ + u0    ];
        c[1] = c0[d*(B_*H_) + lane*H_ + u0 + 1];
    }
    const float* xwT = g_xwT[d];

    // staging map: warp = batch row, lane = quad
    const int sb  = warp;             // 0..31 batch row
    const int kxb = 8 * (sb & 3);

    for (int t = 0; t < T_; t++) {
        const int ph  = t & 1;
        const int txw = d ? (T_ - 1 - t) : t;

        // stage h_prev: b-major LDG.128, conflict-free swizzled STS.128
        {
            const float* cp = g_cur[d][ph] + sb*H_;
            #pragma unroll
            for (int it = 0; it < 4; it++) {
                int uq = lane + it*32;          // 0..127
                float4 v = *(const float4*)(cp + uq*4);
                *(float4*)&hsm[sb*PITCH + ((uq*4) ^ kxb)] = v;
            }
        }

        float xv[8];
        if (kq == 0) {
            const float* bp = xwT + (size_t)txw * G4 * 32 + lane;
            #pragma unroll
            for (int g = 0; g < 4; g++) {
                xv[g*2+0] = __ldcg(bp + (g*H_ + u0    )*32);
                xv[g*2+1] = __ldcg(bp + (g*H_ + u0 + 1)*32);
            }
        }
        __syncthreads();

        unsigned long long acc[8];
        #pragma unroll
        for (int rr = 0; rr < 8; rr++) acc[rr] = 0ull;
        const float* hrow = hsm + lane*PITCH;
        #pragma unroll 4
        for (int q = 0; q < 16; q++) {
            const int k = k0 + q*4;
            ulonglong2 hv = *(const ulonglong2*)&hrow[k ^ kx];
            #pragma unroll
            for (int g = 0; g < 4; g++) {
                ulonglong2 w0 = *(const ulonglong2*)&Wsm[(g*8 + 2*p    )*512 + k];
                ulonglong2 w1 = *(const ulonglong2*)&Wsm[(g*8 + 2*p + 1)*512 + k];
                fma2(acc[g*2+0], w0.x, hv.x); fma2(acc[g*2+0], w0.y, hv.y);
                fma2(acc[g*2+1], w1.x, hv.x); fma2(acc[g*2+1], w1.y, hv.y);
            }
        }
        float av[8];
        #pragma unroll
        for (int rr = 0; rr < 8; rr++) av[rr] = collapse2(acc[rr]);

        if (kq > 0) {
            #pragma unroll
            for (int rr = 0; rr < 8; rr++)
                red[(((kq-1)*4 + p)*8 + rr)*32 + lane] = av[rr];
        }
        __syncthreads();

        if (kq == 0) {
            #pragma unroll
            for (int rr = 0; rr < 8; rr++) {
                float s = av[rr];
                #pragma unroll
                for (int j = 1; j < 8; j++)
                    s += red[(((j-1)*4 + p)*8 + rr)*32 + lane];
                av[rr] = s;
            }
            #pragma unroll
            for (int e = 0; e < 2; e++) {
                float zi = av[0*2+e] + xv[0*2+e];
                float zf = av[1*2+e] + xv[1*2+e];
                float zg = av[2*2+e] + xv[2*2+e];
                float zo = av[3*2+e] + xv[3*2+e];
                float cn = sigm(zf)*c[e] + sigm(zi)*tanhf(zg);
                float hn = sigm(zo)*tanhf(cn);
                c[e] = cn;
                const int u = u0 + e;
                __stcg(&g_cur[d][ph^1][lane*H_ + u], hn);                // state
                __stcg(&g_hT[d][((size_t)txw*H_ + u)*32 + lane], hn);    // archive
            }
        }

        __syncthreads();                     // block's h writes done
        if (t < T_ - 1) {
            // fence-free release/acquire barrier, monotonic counter
            if (tid == 0) {
                int a = atom_add_acqrel(&g_cnt2[d], 1);
                if (a == 64*t + 63) {
                    st_release(&g_gen2[d], t + 1);
                } else {
                    while (ld_acquire(&g_gen2[d]) <= t) { }
                }
            }
            __syncthreads();
        }
    }
}

// ---------------- 4) output projection feats[b,t,k] -------------------------
__global__ void feats_kernel(const float* __restrict__ Wout,
                             const float* __restrict__ bout)
{
    __shared__ float Ws[32*65];    // [k][jj]
    __shared__ float Rs[64*33];    // [jj][b]

    const int tid = threadIdx.x;
    const int b   = tid >> 5;
    const int k   = tid & 31;
    const int t   = blockIdx.x;

    float acc = 0.0f;

    for (int j0 = 0; j0 < 2*H_; j0 += 64) {
        __syncthreads();
        #pragma unroll
        for (int i = tid; i < 32*64; i += 1024) {
            int kk = i >> 6, jj = i & 63;
            Ws[kk*65 + jj] = Wout[kk * (2*H_) + j0 + jj];
        }
        #pragma unroll
        for (int i = tid; i < 64*32; i += 1024) {
            int jj = i >> 5, bb = i & 31;
            int j = j0 + jj;
            float v = (j < H_)
                ? g_hT[0][((size_t)t*H_ + j      )*32 + bb]
                : g_hT[1][((size_t)t*H_ + (j-H_) )*32 + bb];
            Rs[jj*33 + bb] = v;
        }
        __syncthreads();
        #pragma unroll
        for (int jj = 0; jj < 64; jj++)
            acc += Ws[k*65 + jj] * Rs[jj*33 + b];
    }
    g_feats[((size_t)b*T_ + t) * K_ + k] = acc + bout[k];
}

// ---------------- 5) Viterbi decode + backtrack ------------------------------
__global__ void viterbi_kernel(const float* __restrict__ trans,
                               float* __restrict__ out, int path_base)
{
    __shared__ float tr[32][33];
    const int tid = threadIdx.x;
    tr[tid >> 5][tid & 31] = trans[tid];
    __syncthreads();

    const int b    = tid >> 5;
    const int lane = tid & 31;

    float v = (lane == 30) ? 0.0f : NEG_;   // START = 30

    for (int t = 0; t < T_; t++) {
        float ft = g_feats[(size_t)(b * T_ + t) * K_ + lane];
        float best = -3.4e38f;
        int   bp   = 0;
        float vcur = v;
        #pragma unroll
        for (int p = 0; p < 32; p++) {
            float vp = __shfl_sync(0xffffffffu, vcur, p);
            float s = vp + tr[lane][p];
            if (s > best) { best = s; bp = p; }
        }
        v = best + ft;
        g_bp[(size_t)(t * 32 + b) * 32 + lane] = (unsigned char)bp;
    }

    float term = v + tr[31][lane];           // STOP = 31

    float bv = term; int bi = lane;
    #pragma unroll
    for (int off = 16; off > 0; off >>= 1) {
        float ov = __shfl_down_sync(0xffffffffu, bv, off);
        int   oi = __shfl_down_sync(0xffffffffu, bi, off);
        if (ov > bv || (ov == bv && oi < bi)) { bv = ov; bi = oi; }
    }
    bi = __shfl_sync(0xffffffffu, bi, 0);
    bv = __shfl_sync(0xffffffffu, bv, 0);

    if (lane == 0) {
        if (path_base > 0) out[b] = bv;
        int tag = bi;
        for (int t = T_ - 1; t >= 0; t--) {
            out[path_base + b * T_ + t] = (float)tag;
            tag = g_bp[(size_t)(t * 32 + b) * 32 + tag];
        }
    }
}

// ---------------- launch -----------------------------------------------------
extern "C" void kernel_launch(void* const* d_in, const int* in_sizes, int n_in,
                              void* d_out, int out_size)
{
    int unit = 0;
    for (int i = 0; i < n_in; i++) {
        if (in_sizes[i] == 12800000) { unit = 1; break; }
        if (in_sizes[i] == 51200000) { unit = 4; break; }
    }

    int i_sent = -1, i_emb = -1, i_bout = -1, i_tr = -1, sent64 = 0;
    int gih[2], nih = 0, ghh[2], nhh = 0, g2i[2], n2 = 0, g3i[3], n3 = 0;
    if (unit) {
        for (int i = 0; i < n_in; i++) {
            const int s = in_sizes[i] / unit;
            if      (s == 8192)     { if (i_sent < 0) { i_sent = i; sent64 = 0; } }
            else if (s == 16384)    { if (i_sent < 0) { i_sent = i; sent64 = 1; } }
            else if (s == 12800000) { if (i_emb  < 0) i_emb  = i; }
            else if (s == 32)       { if (i_bout < 0) i_bout = i; }
            else if (s == 1024)     { if (i_tr   < 0) i_tr   = i; }
            else if (s == 524288)   { if (nih < 2) gih[nih++] = i; }
            else if (s == 1048576)  { if (nhh < 2) ghh[nhh++] = i; }
            else if (s == 2048)     { if (n2  < 2) g2i[n2++]  = i; }
            else if (s == 32768)    { if (n3  < 3) g3i[n3++]  = i; }
        }
    }
    const int out_elems = (unit == 4) ? out_size / 4 : out_size;

    if (!unit || i_sent < 0 || i_emb < 0 || i_bout < 0 || i_tr < 0 ||
        nih != 2 || nhh != 2 || n2 != 2 || n3 != 3) {
        int n = out_size > 0 ? out_size : 1;
        fill_out<<<(n + 255) / 256, 256>>>((float*)d_out, n, 1.0e6f);
        return;
    }

    int I_Wihf, I_Whhf, I_Wihb, I_Whhb, I_bf, I_bb, I_Wout, I_h0, I_c0;
    if (i_sent < i_emb) {   // dict order
        I_Wihf = gih[0]; I_Wihb = gih[1];
        I_Whhf = ghh[0]; I_Whhb = ghh[1];
        I_bf   = g2i[0]; I_bb   = g2i[1];
        I_Wout = g3i[0]; I_h0   = g3i[1]; I_c0 = g3i[2];
    } else {                // name-sorted order
        I_Whhb = ghh[0]; I_Whhf = ghh[1];
        I_Wihb = gih[0]; I_Wihf = gih[1];
        I_bb   = g2i[0]; I_bf   = g2i[1];
        I_Wout = g3i[0]; I_c0   = g3i[1]; I_h0 = g3i[2];
    }

    const void*  sentence = d_in[i_sent];
    const float* emb      = (const float*)d_in[i_emb];
    const float* W_ih_f   = (const float*)d_in[I_Wihf];
    const float* W_hh_f   = (const float*)d_in[I_Whhf];
    const float* b_f      = (const float*)d_in[I_bf];
    const float* W_ih_b   = (const float*)d_in[I_Wihb];
    const float* W_hh_b   = (const float*)d_in[I_Whhb];
    const float* b_b      = (const float*)d_in[I_bb];
    const float* W_out    = (const float*)d_in[I_Wout];
    const float* b_out    = (const float*)d_in[i_bout];
    const float* trans    = (const float*)d_in[i_tr];
    const float* h0       = (const float*)d_in[I_h0];
    const float* c0       = (const float*)d_in[I_c0];
    float* out = (float*)d_out;

    const int path_base = (out_elems >= B_ + B_*T_) ? B_ : 0;

    const int SMEM_G = (2048 + 128*129) * 4;                 // 74240 B
    const int SMEM_P = (32*512 + 32*PITCH + 28*8*32) * 4;    // 160256 B
    cudaFuncSetAttribute(gemm_xw,
                         cudaFuncAttributeMaxDynamicSharedMemorySize, SMEM_G);
    cudaFuncSetAttribute(lstm_persist,
                         cudaFuncAttributeMaxDynamicSharedMemorySize, SMEM_P);

    gemm_xw<<<dim3(32, 64), 256, SMEM_G>>>(sentence, sent64, emb,
                                           W_ih_f, W_ih_b, b_f, b_b);
    init_state<<<64, 512>>>(h0);
    lstm_persist<<<128, 1024, SMEM_P>>>(W_hh_f, W_hh_b, c0);
    feats_kernel<<<T_, 1024>>>(W_out, b_out);
    viterbi_kernel<<<1, 1024>>>(trans, out, path_base);
}

// round 13
// speedup vs baseline: 1.4344x; 1.0097x over previous
#include <cuda_runtime.h>
#include <math.h>
#include <stdint.h>

#define B_  32
#define T_  256
#define E_  256            // V,E,H,K = 50000,256,512,32
#define H_  512
#define K_  32
#define V_  50000
#define G4  2048           // 4*H
#define M_  (T_*B_)        // 8192 tokens
#define NEG_ -10000.0f
#define PITCH 516          // hsm row pitch (floats)

// ---------------- scratch (static device globals; no allocation) -------------
__device__ float g_xwT[2][M_*G4];         // [d][(t*2048+n)*32+b]
__device__ float g_hT [2][M_*H_];         // [d][(t*512+u)*32+b]  archive (feats)
__device__ float g_cur[2][2][B_*H_];      // [d][phase][b*512+u]  b-major state
__device__ float g_feats[B_*T_*K_];       // [m][k], m=b*T+t
__device__ unsigned char g_bp[T_*B_*K_];
__device__ int g_cnt2[2];                 // monotonic arrival counters
__device__ int g_gen2[2];                 // release generations

__device__ __forceinline__ float sigm(float x){ return 1.0f/(1.0f+expf(-x)); }

__device__ __forceinline__ void fma2(unsigned long long &acc,
                                     unsigned long long a, unsigned long long b){
    asm("fma.rn.f32x2 %0, %1, %2, %0;" : "+l"(acc) : "l"(a), "l"(b));
}
__device__ __forceinline__ unsigned long long dup2(float a){
    unsigned long long d;
    asm("mov.b64 %0, {%1, %1};" : "=l"(d) : "f"(a));
    return d;
}
__device__ __forceinline__ float collapse2(unsigned long long v){
    float lo, hi;
    asm("mov.b64 {%0, %1}, %2;" : "=f"(lo), "=f"(hi) : "l"(v));
    return lo + hi;
}
__device__ __forceinline__ int atom_add_acqrel(int* a, int v){
    int old;
    asm volatile("atom.add.acq_rel.gpu.global.s32 %0, [%1], %2;"
                 : "=r"(old) : "l"(a), "r"(v) : "memory");
    return old;
}
__device__ __forceinline__ int ld_acquire(int* a){
    int v;
    asm volatile("ld.acquire.gpu.global.s32 %0, [%1];"
                 : "=r"(v) : "l"(a) : "memory");
    return v;
}
__device__ __forceinline__ void st_release(int* a, int v){
    asm volatile("st.release.gpu.global.s32 [%0], %1;"
                 :: "l"(a), "r"(v) : "memory");
}

__global__ void fill_out(float* out, int n, float val)
{
    int i = blockIdx.x * blockDim.x + threadIdx.x;
    if (i < n) out[i] = val;
}

// ---------------- 1) embedding-gather + input GEMM + fused transpose --------
__global__ void gemm_xw(const void* __restrict__ sentence, int sent64,
                        const float* __restrict__ emb,
                        const float* __restrict__ Wf,
                        const float* __restrict__ Wb,
                        const float* __restrict__ bf,
                        const float* __restrict__ bb)
{
    extern __shared__ float smg[];
    float* As   = smg;            // [8][128]
    float* Bs   = smg + 1024;     // [8][128]
    float* tile = smg + 2048;     // [128][129]

    const int bx = blockIdx.x;    // 0..31 (N tiles)
    const int by = blockIdx.y;    // 0..63 (M tiles)
    const int tid = threadIdx.x;
    const int tx = tid & 15;
    const int ty = tid >> 4;

    const int arow  = tid >> 1;
    const int acol4 = (tid & 1) * 4;
    const int r  = by * 128 + arow;
    const int tt = r >> 5;
    const int bb_ = r & 31;
    long long w64 = sent64 ? ((const long long*)sentence)[bb_ * T_ + tt]
                           : (long long)((const int*)sentence)[bb_ * T_ + tt];
    unsigned int word = (unsigned int)w64;
    if (word >= V_) word = 0;
    const float* aptr = emb + (size_t)word * E_;

    const int brow  = tid >> 1;
    const int bcol4 = (tid & 1) * 4;
    const int n = bx * 128 + brow;
    const float* wptr = (n < G4) ? (Wf + (size_t)n * E_)
                                 : (Wb + (size_t)(n - G4) * E_);

    unsigned long long acc2[8][4];
    #pragma unroll
    for (int i = 0; i < 8; i++)
        #pragma unroll
        for (int j = 0; j < 4; j++) acc2[i][j] = 0ull;

    for (int k0 = 0; k0 < E_; k0 += 8) {
        float4 a4 = *(const float4*)(aptr + k0 + acol4);
        float4 b4 = *(const float4*)(wptr + k0 + bcol4);
        __syncthreads();
        As[(acol4+0)*128 + arow] = a4.x; As[(acol4+1)*128 + arow] = a4.y;
        As[(acol4+2)*128 + arow] = a4.z; As[(acol4+3)*128 + arow] = a4.w;
        Bs[(bcol4+0)*128 + brow] = b4.x; Bs[(bcol4+1)*128 + brow] = b4.y;
        Bs[(bcol4+2)*128 + brow] = b4.z; Bs[(bcol4+3)*128 + brow] = b4.w;
        __syncthreads();
        #pragma unroll
        for (int k = 0; k < 8; k++) {
            float4 a0 = *(const float4*)&As[k*128 + ty*8];
            float4 a1 = *(const float4*)&As[k*128 + ty*8 + 4];
            ulonglong2 bq0 = *(const ulonglong2*)&Bs[k*128 + tx*8];
            ulonglong2 bq1 = *(const ulonglong2*)&Bs[k*128 + tx*8 + 4];
            float av[8] = {a0.x,a0.y,a0.z,a0.w,a1.x,a1.y,a1.z,a1.w};
            #pragma unroll
            for (int i = 0; i < 8; i++) {
                unsigned long long ap = dup2(av[i]);
                fma2(acc2[i][0], ap, bq0.x);
                fma2(acc2[i][1], ap, bq0.y);
                fma2(acc2[i][2], ap, bq1.x);
                fma2(acc2[i][3], ap, bq1.y);
            }
        }
    }

    __syncthreads();
    #pragma unroll
    for (int i = 0; i < 8; i++) {
        const int ml = ty*8 + i;
        #pragma unroll
        for (int jp = 0; jp < 4; jp++) {
            float lo, hi;
            asm("mov.b64 {%0, %1}, %2;" : "=f"(lo), "=f"(hi) : "l"(acc2[i][jp]));
            tile[ml*129 + tx*8 + jp*2    ] = lo;
            tile[ml*129 + tx*8 + jp*2 + 1] = hi;
        }
    }
    __syncthreads();

    const int d = bx >> 4;
    const int jjbase = bx * 128 - d * G4;
    const float* bias = d ? bb : bf;
    float* outp = g_xwT[d];
    const int wid  = tid >> 5;
    const int lane = tid & 31;
    #pragma unroll 8
    for (int it = 0; it < 64; it++) {
        int group = wid*64 + it;
        int nl = group >> 2;
        int tg = group & 3;
        float v = tile[(tg*32 + lane)*129 + nl] + bias[jjbase + nl];
        outp[((size_t)(by*4 + tg)*G4 + jjbase + nl)*32 + lane] = v;
    }
}

// ---------------- 2) init: h0 -> cur[phase 0] (identity copy), barrier ------
__global__ void init_state(const float* __restrict__ h0)
{
    int i = blockIdx.x * blockDim.x + threadIdx.x;
    if (i == 0) { g_cnt2[0] = 0; g_cnt2[1] = 0; g_gen2[0] = 0; g_gen2[1] = 0; }
    if (i < 2*B_*H_) {
        int d = i / (B_*H_);
        g_cur[d][0][i - d*(B_*H_)] = h0[i];
    }
}

// ---------------- 3) persistent bidirectional LSTM recurrence ---------------
// 128 blocks x 512 threads (16 warps). Block = 8 units x 4 gates, one dir.
// warp = (p=warp&3 unit-pair, kq=warp>>2 k-quarter);
// lane = (kk=lane>>3 k-slice, bb=lane&7 batch-low). Thread: 8 rows x 4 batches.
__global__ void __launch_bounds__(512, 1)
lstm_persist(const float* __restrict__ Whhf,
             const float* __restrict__ Whhb,
             const float* __restrict__ c0)
{
    extern __shared__ float sm[];
    float* Wsm  = sm;                  // [32][512], per-(row,kq) c-interleaved
    float* hsm  = Wsm + 32*512;        // [32][PITCH], row=batch (XOR swizzled)
    float* red  = hsm + 32*PITCH;      // [3][4][8][32] k-quarter partials
    float* xwsm = red + 3*4*8*32;      // [32 n_local][32 b]

    const int tid  = threadIdx.x;
    const int bid  = blockIdx.x;
    const int warp = tid >> 5;
    const int lane = tid & 31;
    const int d    = bid >> 6;
    const int ub   = (bid & 63) * 8;
    const float* W = d ? Whhb : Whhf;

    // W load, k-permuted within each (row, 128k region):
    // k = kq*128 + kk*32 + c*4 + w  ->  pos = kq*128 + c*16 + kk*4 + w
    for (int i = tid; i < 32*512; i += 512) {
        int rr = i >> 9, k = i & 511;
        int gg = rr >> 3, ii = rr & 7;
        int kk = (k >> 5) & 3, c = (k >> 2) & 7, w = k & 3;
        int pos = rr*512 + (k & ~127) + c*16 + kk*4 + w;
        Wsm[pos] = W[(size_t)(gg*H_ + ub + ii)*H_ + k];
    }

    const int p  = warp & 3;
    const int kq = warp >> 2;         // 0..3
    const int k0 = kq * 128;
    const int u0 = ub + 2*p;
    const int bb = lane & 7;
    const int kk = lane >> 3;

    // cell state: [e][j], kk-replicated across lanes (identical arithmetic)
    float cst[2][4];
    if (kq == 0) {
        #pragma unroll
        for (int e = 0; e < 2; e++)
            #pragma unroll
            for (int j = 0; j < 4; j++)
                cst[e][j] = c0[d*(B_*H_) + (bb + 8*j)*H_ + u0 + e];
    }
    const float* xwT = g_xwT[d];

    // staging map (identical to proven R11/R12): sb row, suq quad base
    const int sb  = tid >> 4;
    const int suq = tid & 15;
    const int kxb = 8 * (sb & 3);

    for (int t = 0; t < T_; t++) {
        const int ph  = t & 1;
        const int txw = d ? (T_ - 1 - t) : t;

        // (1) xw LDG issue early (all warps, 2 rows of 32 each, coalesced)
        float xv0, xv1;
        {
            const float* bp = xwT + (size_t)txw * G4 * 32;
            int nl0 = 2*warp, nl1 = 2*warp + 1;
            xv0 = __ldcg(bp + (size_t)((nl0 >> 3)*H_ + ub + (nl0 & 7))*32 + lane);
            xv1 = __ldcg(bp + (size_t)((nl1 >> 3)*H_ + ub + (nl1 & 7))*32 + lane);
        }

        // (2) stage h_prev (b-major LDG.128 + conflict-free swizzled STS.128)
        {
            const float* cp = g_cur[d][ph] + sb*H_;
            #pragma unroll
            for (int it = 0; it < 8; it++) {
                int uq = suq + it*16;
                float4 v = *(const float4*)(cp + uq*4);
                *(float4*)&hsm[sb*PITCH + ((uq*4) ^ kxb)] = v;
            }
        }

        // (3) deposit xw into smem
        xwsm[(2*warp    )*32 + lane] = xv0;
        xwsm[(2*warp + 1)*32 + lane] = xv1;
        __syncthreads();

        // (4) compute: 8 rows x 4 batches per thread over k-slice
        unsigned long long acc[4][2][4];
        #pragma unroll
        for (int g = 0; g < 4; g++)
            #pragma unroll
            for (int e = 0; e < 2; e++)
                #pragma unroll
                for (int j = 0; j < 4; j++) acc[g][e][j] = 0ull;

        #pragma unroll
        for (int c = 0; c < 8; c++) {
            ulonglong2 hq[4];
            #pragma unroll
            for (int j = 0; j < 4; j++) {
                int b = bb + 8*j;
                int pos = (k0 + kk*32 + c*4) ^ (8*(b & 3));
                hq[j] = *(const ulonglong2*)&hsm[b*PITCH + pos];
            }
            #pragma unroll
            for (int g = 0; g < 4; g++)
                #pragma unroll
                for (int e = 0; e < 2; e++) {
                    int rr = g*8 + 2*p + e;
                    ulonglong2 wq = *(const ulonglong2*)
                        &Wsm[rr*512 + k0 + c*16 + kk*4];
                    #pragma unroll
                    for (int j = 0; j < 4; j++) {
                        fma2(acc[g][e][j], wq.x, hq[j].x);
                        fma2(acc[g][e][j], wq.y, hq[j].y);
                    }
                }
        }

        // collapse + within-warp kk-reduction (2 bfly rounds over lane bits 3,4)
        float av[4][2][4];
        #pragma unroll
        for (int g = 0; g < 4; g++)
            #pragma unroll
            for (int e = 0; e < 2; e++)
                #pragma unroll
                for (int j = 0; j < 4; j++) {
                    float v = collapse2(acc[g][e][j]);
                    v += __shfl_xor_sync(0xffffffffu, v, 8);
                    v += __shfl_xor_sync(0xffffffffu, v, 16);
                    av[g][e][j] = v;
                }

        if (kq > 0 && kk == 0) {
            #pragma unroll
            for (int g = 0; g < 4; g++)
                #pragma unroll
                for (int e = 0; e < 2; e++)
                    #pragma unroll
                    for (int j = 0; j < 4; j++)
                        red[(((kq-1)*4 + p)*8 + g*2 + e)*32 + bb + 8*j]
                            = av[g][e][j];
        }
        __syncthreads();

        if (kq == 0) {
            #pragma unroll
            for (int g = 0; g < 4; g++)
                #pragma unroll
                for (int e = 0; e < 2; e++)
                    #pragma unroll
                    for (int j = 0; j < 4; j++) {
                        float s = av[g][e][j];
                        #pragma unroll
                        for (int jj = 0; jj < 3; jj++)
                            s += red[((jj*4 + p)*8 + g*2 + e)*32 + bb + 8*j];
                        av[g][e][j] = s;
                    }
            #pragma unroll
            for (int e = 0; e < 2; e++)
                #pragma unroll
                for (int j = 0; j < 4; j++) {
                    int b = bb + 8*j;
                    float zi = av[0][e][j] + xwsm[(0*8 + 2*p + e)*32 + b];
                    float zf = av[1][e][j] + xwsm[(1*8 + 2*p + e)*32 + b];
                    float zg = av[2][e][j] + xwsm[(2*8 + 2*p + e)*32 + b];
                    float zo = av[3][e][j] + xwsm[(3*8 + 2*p + e)*32 + b];
                    float cn = sigm(zf)*cst[e][j] + sigm(zi)*tanhf(zg);
                    float hn = sigm(zo)*tanhf(cn);
                    cst[e][j] = cn;
                    if (kk == 0) {
                        const int u = u0 + e;
                        __stcg(&g_cur[d][ph^1][b*H_ + u], hn);
                        __stcg(&g_hT[d][((size_t)txw*H_ + u)*32 + b], hn);
                    }
                }
        }

        __syncthreads();                      // block's h writes / hsm reads done
        if (t < T_ - 1) {
            if (tid == 0) {
                int a = atom_add_acqrel(&g_cnt2[d], 1);
                if (a == 64*t + 63) {
                    st_release(&g_gen2[d], t + 1);
                } else {
                    while (ld_acquire(&g_gen2[d]) <= t) { }
                }
            }
            __syncthreads();
        }
    }
}

// ---------------- 4) output projection feats[b,t,k] -------------------------
__global__ void feats_kernel(const float* __restrict__ Wout,
                             const float* __restrict__ bout)
{
    __shared__ float Ws[32*65];    // [k][jj]
    __shared__ float Rs[64*33];    // [jj][b]

    const int tid = threadIdx.x;
    const int b   = tid >> 5;
    const int k   = tid & 31;
    const int t   = blockIdx.x;

    float acc = 0.0f;

    for (int j0 = 0; j0 < 2*H_; j0 += 64) {
        __syncthreads();
        #pragma unroll
        for (int i = tid; i < 32*64; i += 1024) {
            int kk = i >> 6, jj = i & 63;
            Ws[kk*65 + jj] = Wout[kk * (2*H_) + j0 + jj];
        }
        #pragma unroll
        for (int i = tid; i < 64*32; i += 1024) {
            int jj = i >> 5, bb = i & 31;
            int j = j0 + jj;
            float v = (j < H_)
                ? g_hT[0][((size_t)t*H_ + j      )*32 + bb]
                : g_hT[1][((size_t)t*H_ + (j-H_) )*32 + bb];
            Rs[jj*33 + bb] = v;
        }
        __syncthreads();
        #pragma unroll
        for (int jj = 0; jj < 64; jj++)
            acc += Ws[k*65 + jj] * Rs[jj*33 + b];
    }
    g_feats[((size_t)b*T_ + t) * K_ + k] = acc + bout[k];
}

// ---------------- 5) Viterbi decode + backtrack ------------------------------
__global__ void viterbi_kernel(const float* __restrict__ trans,
                               float* __restrict__ out, int path_base)
{
    __shared__ float tr[32][33];
    const int tid = threadIdx.x;
    tr[tid >> 5][tid & 31] = trans[tid];
    __syncthreads();

    const int b    = tid >> 5;
    const int lane = tid & 31;

    float v = (lane == 30) ? 0.0f : NEG_;   // START = 30

    for (int t = 0; t < T_; t++) {
        float ft = g_feats[(size_t)(b * T_ + t) * K_ + lane];
        float best = -3.4e38f;
        int   bp   = 0;
        float vcur = v;
        #pragma unroll
        for (int p = 0; p < 32; p++) {
            float vp = __shfl_sync(0xffffffffu, vcur, p);
            float s = vp + tr[lane][p];
            if (s > best) { best = s; bp = p; }
        }
        v = best + ft;
        g_bp[(size_t)(t * 32 + b) * 32 + lane] = (unsigned char)bp;
    }

    float term = v + tr[31][lane];           // STOP = 31

    float bv = term; int bi = lane;
    #pragma unroll
    for (int off = 16; off > 0; off >>= 1) {
        float ov = __shfl_down_sync(0xffffffffu, bv, off);
        int   oi = __shfl_down_sync(0xffffffffu, bi, off);
        if (ov > bv || (ov == bv && oi < bi)) { bv = ov; bi = oi; }
    }
    bi = __shfl_sync(0xffffffffu, bi, 0);
    bv = __shfl_sync(0xffffffffu, bv, 0);

    if (lane == 0) {
        if (path_base > 0) out[b] = bv;
        int tag = bi;
        for (int t = T_ - 1; t >= 0; t--) {
            out[path_base + b * T_ + t] = (float)tag;
            tag = g_bp[(size_t)(t * 32 + b) * 32 + tag];
        }
    }
}

// ---------------- launch -----------------------------------------------------
extern "C" void kernel_launch(void* const* d_in, const int* in_sizes, int n_in,
                              void* d_out, int out_size)
{
    int unit = 0;
    for (int i = 0; i < n_in; i++) {
        if (in_sizes[i] == 12800000) { unit = 1; break; }
        if (in_sizes[i] == 51200000) { unit = 4; break; }
    }

    int i_sent = -1, i_emb = -1, i_bout = -1, i_tr = -1, sent64 = 0;
    int gih[2], nih = 0, ghh[2], nhh = 0, g2i[2], n2 = 0, g3i[3], n3 = 0;
    if (unit) {
        for (int i = 0; i < n_in; i++) {
            const int s = in_sizes[i] / unit;
            if      (s == 8192)     { if (i_sent < 0) { i_sent = i; sent64 = 0; } }
            else if (s == 16384)    { if (i_sent < 0) { i_sent = i; sent64 = 1; } }
            else if (s == 12800000) { if (i_emb  < 0) i_emb  = i; }
            else if (s == 32)       { if (i_bout < 0) i_bout = i; }
            else if (s == 1024)     { if (i_tr   < 0) i_tr   = i; }
            else if (s == 524288)   { if (nih < 2) gih[nih++] = i; }
            else if (s == 1048576)  { if (nhh < 2) ghh[nhh++] = i; }
            else if (s == 2048)     { if (n2  < 2) g2i[n2++]  = i; }
            else if (s == 32768)    { if (n3  < 3) g3i[n3++]  = i; }
        }
    }
    const int out_elems = (unit == 4) ? out_size / 4 : out_size;

    if (!unit || i_sent < 0 || i_emb < 0 || i_bout < 0 || i_tr < 0 ||
        nih != 2 || nhh != 2 || n2 != 2 || n3 != 3) {
        int n = out_size > 0 ? out_size : 1;
        fill_out<<<(n + 255) / 256, 256>>>((float*)d_out, n, 1.0e6f);
        return;
    }

    int I_Wihf, I_Whhf, I_Wihb, I_Whhb, I_bf, I_bb, I_Wout, I_h0, I_c0;
    if (i_sent < i_emb) {   // dict order
        I_Wihf = gih[0]; I_Wihb = gih[1];
        I_Whhf = ghh[0]; I_Whhb = ghh[1];
        I_bf   = g2i[0]; I_bb   = g2i[1];
        I_Wout = g3i[0]; I_h0   = g3i[1]; I_c0 = g3i[2];
    } else {                // name-sorted order
        I_Whhb = ghh[0]; I_Whhf = ghh[1];
        I_Wihb = gih[0]; I_Wihf = gih[1];
        I_bb   = g2i[0]; I_bf   = g2i[1];
        I_Wout = g3i[0]; I_c0   = g3i[1]; I_h0 = g3i[2];
    }

    const void*  sentence = d_in[i_sent];
    const float* emb      = (const float*)d_in[i_emb];
    const float* W_ih_f   = (const float*)d_in[I_Wihf];
    const float* W_hh_f   = (const float*)d_in[I_Whhf];
    const float* b_f      = (const float*)d_in[I_bf];
    const float* W_ih_b   = (const float*)d_in[I_Wihb];
    const float* W_hh_b   = (const float*)d_in[I_Whhb];
    const float* b_b      = (const float*)d_in[I_bb];
    const float* W_out    = (const float*)d_in[I_Wout];
    const float* b_out    = (const float*)d_in[i_bout];
    const float* trans    = (const float*)d_in[i_tr];
    const float* h0       = (const float*)d_in[I_h0];
    const float* c0       = (const float*)d_in[I_c0];
    float* out = (float*)d_out;

    const int path_base = (out_elems >= B_ + B_*T_) ? B_ : 0;

    const int SMEM_G = (2048 + 128*129) * 4;                          // 74240 B
    const int SMEM_P = (32*512 + 32*PITCH + 3*4*8*32 + 32*32) * 4;    // 147968 B
    cudaFuncSetAttribute(gemm_xw,
                         cudaFuncAttributeMaxDynamicSharedMemorySize, SMEM_G);
    cudaFuncSetAttribute(lstm_persist,
                         cudaFuncAttributeMaxDynamicSharedMemorySize, SMEM_P);

    gemm_xw<<<dim3(32, 64), 256, SMEM_G>>>(sentence, sent64, emb,
                                           W_ih_f, W_ih_b, b_f, b_b);
    init_state<<<64, 512>>>(h0);
    lstm_persist<<<128, 512, SMEM_P>>>(W_hh_f, W_hh_b, c0);
    feats_kernel<<<T_, 1024>>>(W_out, b_out);
    viterbi_kernel<<<1, 1024>>>(trans, out, path_base);
}

// round 14
// speedup vs baseline: 1.4392x; 1.0034x over previous
#include <cuda_runtime.h>
#include <math.h>
#include <stdint.h>

#define B_  32
#define T_  256
#define E_  256            // V,E,H,K = 50000,256,512,32
#define H_  512
#define K_  32
#define V_  50000
#define G4  2048           // 4*H
#define M_  (T_*B_)        // 8192 tokens
#define NEG_ -10000.0f
#define PITCH 516          // hsm row pitch (floats)

// ---------------- scratch (static device globals; no allocation) -------------
__device__ float g_xwT[2][M_*G4];         // [d][(t*2048+n)*32+b]
__device__ float g_hT [2][M_*H_];         // [d][(t*512+u)*32+b]  archive (feats)
__device__ float g_cur[2][2][B_*H_];      // [d][phase][b*512+u]  b-major state
__device__ float g_feats[B_*T_*K_];       // [m][k], m=b*T+t
__device__ unsigned char g_bp[T_*B_*K_];
__device__ int g_cnt2[2];                 // monotonic arrival counters
__device__ int g_gen2[2];                 // release generations

__device__ __forceinline__ float sigm(float x){ return 1.0f/(1.0f+expf(-x)); }

__device__ __forceinline__ void fma2(unsigned long long &acc,
                                     unsigned long long a, unsigned long long b){
    asm("fma.rn.f32x2 %0, %1, %2, %0;" : "+l"(acc) : "l"(a), "l"(b));
}
__device__ __forceinline__ unsigned long long dup2(float a){
    unsigned long long d;
    asm("mov.b64 %0, {%1, %1};" : "=l"(d) : "f"(a));
    return d;
}
__device__ __forceinline__ float collapse2(unsigned long long v){
    float lo, hi;
    asm("mov.b64 {%0, %1}, %2;" : "=f"(lo), "=f"(hi) : "l"(v));
    return lo + hi;
}
__device__ __forceinline__ int atom_add_acqrel(int* a, int v){
    int old;
    asm volatile("atom.add.acq_rel.gpu.global.s32 %0, [%1], %2;"
                 : "=r"(old) : "l"(a), "r"(v) : "memory");
    return old;
}
__device__ __forceinline__ int ld_acquire(int* a){
    int v;
    asm volatile("ld.acquire.gpu.global.s32 %0, [%1];"
                 : "=r"(v) : "l"(a) : "memory");
    return v;
}
__device__ __forceinline__ void st_release(int* a, int v){
    asm volatile("st.release.gpu.global.s32 [%0], %1;"
                 :: "l"(a), "r"(v) : "memory");
}

__global__ void fill_out(float* out, int n, float val)
{
    int i = blockIdx.x * blockDim.x + threadIdx.x;
    if (i < n) out[i] = val;
}

// ---------------- 1) embedding-gather + input GEMM + fused transpose --------
// Double-buffered smem, 1 syncthreads/iter, 2 blocks/SM.
__global__ void __launch_bounds__(256, 2)
gemm_xw(const void* __restrict__ sentence, int sent64,
        const float* __restrict__ emb,
        const float* __restrict__ Wf,
        const float* __restrict__ Wb,
        const float* __restrict__ bf,
        const float* __restrict__ bb)
{
    extern __shared__ float smg[];
    float* As0  = smg;            // [2][8][128]
    float* Bs0  = smg + 2048;     // [2][8][128]
    float* tile = smg + 4096;     // [128][129]

    const int bx = blockIdx.x;    // 0..31 (N tiles)
    const int by = blockIdx.y;    // 0..63 (M tiles)
    const int tid = threadIdx.x;
    const int tx = tid & 15;
    const int ty = tid >> 4;

    const int arow  = tid >> 1;
    const int acol4 = (tid & 1) * 4;
    const int r  = by * 128 + arow;
    const int tt = r >> 5;
    const int bb_ = r & 31;
    long long w64 = sent64 ? ((const long long*)sentence)[bb_ * T_ + tt]
                           : (long long)((const int*)sentence)[bb_ * T_ + tt];
    unsigned int word = (unsigned int)w64;
    if (word >= V_) word = 0;
    const float* aptr = emb + (size_t)word * E_;

    const int brow  = tid >> 1;
    const int bcol4 = (tid & 1) * 4;
    const int n = bx * 128 + brow;
    const float* wptr = (n < G4) ? (Wf + (size_t)n * E_)
                                 : (Wb + (size_t)(n - G4) * E_);

    unsigned long long acc2[8][4];
    #pragma unroll
    for (int i = 0; i < 8; i++)
        #pragma unroll
        for (int j = 0; j < 4; j++) acc2[i][j] = 0ull;

    // prime buffer 0 with k-block 0
    {
        float4 a4 = *(const float4*)(aptr + acol4);
        float4 b4 = *(const float4*)(wptr + bcol4);
        As0[(acol4+0)*128 + arow] = a4.x; As0[(acol4+1)*128 + arow] = a4.y;
        As0[(acol4+2)*128 + arow] = a4.z; As0[(acol4+3)*128 + arow] = a4.w;
        Bs0[(bcol4+0)*128 + brow] = b4.x; Bs0[(bcol4+1)*128 + brow] = b4.y;
        Bs0[(bcol4+2)*128 + brow] = b4.z; Bs0[(bcol4+3)*128 + brow] = b4.w;
    }
    __syncthreads();

    for (int k0 = 0; k0 < E_; k0 += 8) {
        const int buf = (k0 >> 3) & 1;
        const float* As = As0 + buf*1024;
        const float* Bs = Bs0 + buf*1024;

        // prefetch next k-block into registers (overlaps with compute)
        float4 a4n, b4n;
        const bool more = (k0 + 8 < E_);
        if (more) {
            a4n = *(const float4*)(aptr + k0 + 8 + acol4);
            b4n = *(const float4*)(wptr + k0 + 8 + bcol4);
        }

        #pragma unroll
        for (int k = 0; k < 8; k++) {
            float4 a0 = *(const float4*)&As[k*128 + ty*8];
            float4 a1 = *(const float4*)&As[k*128 + ty*8 + 4];
            ulonglong2 bq0 = *(const ulonglong2*)&Bs[k*128 + tx*8];
            ulonglong2 bq1 = *(const ulonglong2*)&Bs[k*128 + tx*8 + 4];
            float av[8] = {a0.x,a0.y,a0.z,a0.w,a1.x,a1.y,a1.z,a1.w};
            #pragma unroll
            for (int i = 0; i < 8; i++) {
                unsigned long long ap = dup2(av[i]);
                fma2(acc2[i][0], ap, bq0.x);
                fma2(acc2[i][1], ap, bq0.y);
                fma2(acc2[i][2], ap, bq1.x);
                fma2(acc2[i][3], ap, bq1.y);
            }
        }

        if (more) {
            float* An = As0 + (buf^1)*1024;
            float* Bn = Bs0 + (buf^1)*1024;
            An[(acol4+0)*128 + arow] = a4n.x; An[(acol4+1)*128 + arow] = a4n.y;
            An[(acol4+2)*128 + arow] = a4n.z; An[(acol4+3)*128 + arow] = a4n.w;
            Bn[(bcol4+0)*128 + brow] = b4n.x; Bn[(bcol4+1)*128 + brow] = b4n.y;
            Bn[(bcol4+2)*128 + brow] = b4n.z; Bn[(bcol4+3)*128 + brow] = b4n.w;
        }
        __syncthreads();
    }

    // stage results into smem tile (m_local x n_local)
    #pragma unroll
    for (int i = 0; i < 8; i++) {
        const int ml = ty*8 + i;
        #pragma unroll
        for (int jp = 0; jp < 4; jp++) {
            float lo, hi;
            asm("mov.b64 {%0, %1}, %2;" : "=f"(lo), "=f"(hi) : "l"(acc2[i][jp]));
            tile[ml*129 + tx*8 + jp*2    ] = lo;
            tile[ml*129 + tx*8 + jp*2 + 1] = hi;
        }
    }
    __syncthreads();

    const int d = bx >> 4;
    const int jjbase = bx * 128 - d * G4;
    const float* bias = d ? bb : bf;
    float* outp = g_xwT[d];
    const int wid  = tid >> 5;
    const int lane = tid & 31;
    #pragma unroll 8
    for (int it = 0; it < 64; it++) {
        int group = wid*64 + it;
        int nl = group >> 2;
        int tg = group & 3;
        float v = tile[(tg*32 + lane)*129 + nl] + bias[jjbase + nl];
        outp[((size_t)(by*4 + tg)*G4 + jjbase + nl)*32 + lane] = v;
    }
}

// ---------------- 2) init: h0 -> cur[phase 0] (identity copy), barrier ------
__global__ void init_state(const float* __restrict__ h0)
{
    int i = blockIdx.x * blockDim.x + threadIdx.x;
    if (i == 0) { g_cnt2[0] = 0; g_cnt2[1] = 0; g_gen2[0] = 0; g_gen2[1] = 0; }
    if (i < 2*B_*H_) {
        int d = i / (B_*H_);
        g_cur[d][0][i - d*(B_*H_)] = h0[i];
    }
}

// ---------------- 3) persistent bidirectional LSTM recurrence ---------------
// (frozen from R13: 128 x 512, c-interleaved W, kk/bb lane split)
__global__ void __launch_bounds__(512, 1)
lstm_persist(const float* __restrict__ Whhf,
             const float* __restrict__ Whhb,
             const float* __restrict__ c0)
{
    extern __shared__ float sm[];
    float* Wsm  = sm;                  // [32][512], per-(row,kq) c-interleaved
    float* hsm  = Wsm + 32*512;        // [32][PITCH], row=batch (XOR swizzled)
    float* red  = hsm + 32*PITCH;      // [3][4][8][32] k-quarter partials
    float* xwsm = red + 3*4*8*32;      // [32 n_local][32 b]

    const int tid  = threadIdx.x;
    const int bid  = blockIdx.x;
    const int warp = tid >> 5;
    const int lane = tid & 31;
    const int d    = bid >> 6;
    const int ub   = (bid & 63) * 8;
    const float* W = d ? Whhb : Whhf;

    for (int i = tid; i < 32*512; i += 512) {
        int rr = i >> 9, k = i & 511;
        int gg = rr >> 3, ii = rr & 7;
        int kk = (k >> 5) & 3, c = (k >> 2) & 7, w = k & 3;
        int pos = rr*512 + (k & ~127) + c*16 + kk*4 + w;
        Wsm[pos] = W[(size_t)(gg*H_ + ub + ii)*H_ + k];
    }

    const int p  = warp & 3;
    const int kq = warp >> 2;
    const int k0 = kq * 128;
    const int u0 = ub + 2*p;
    const int bb = lane & 7;
    const int kk = lane >> 3;

    float cst[2][4];
    if (kq == 0) {
        #pragma unroll
        for (int e = 0; e < 2; e++)
            #pragma unroll
            for (int j = 0; j < 4; j++)
                cst[e][j] = c0[d*(B_*H_) + (bb + 8*j)*H_ + u0 + e];
    }
    const float* xwT = g_xwT[d];

    const int sb  = tid >> 4;
    const int suq = tid & 15;
    const int kxb = 8 * (sb & 3);

    for (int t = 0; t < T_; t++) {
        const int ph  = t & 1;
        const int txw = d ? (T_ - 1 - t) : t;

        float xv0, xv1;
        {
            const float* bp = xwT + (size_t)txw * G4 * 32;
            int nl0 = 2*warp, nl1 = 2*warp + 1;
            xv0 = __ldcg(bp + (size_t)((nl0 >> 3)*H_ + ub + (nl0 & 7))*32 + lane);
            xv1 = __ldcg(bp + (size_t)((nl1 >> 3)*H_ + ub + (nl1 & 7))*32 + lane);
        }

        {
            const float* cp = g_cur[d][ph] + sb*H_;
            #pragma unroll
            for (int it = 0; it < 8; it++) {
                int uq = suq + it*16;
                float4 v = *(const float4*)(cp + uq*4);
                *(float4*)&hsm[sb*PITCH + ((uq*4) ^ kxb)] = v;
            }
        }

        xwsm[(2*warp    )*32 + lane] = xv0;
        xwsm[(2*warp + 1)*32 + lane] = xv1;
        __syncthreads();

        unsigned long long acc[4][2][4];
        #pragma unroll
        for (int g = 0; g < 4; g++)
            #pragma unroll
            for (int e = 0; e < 2; e++)
                #pragma unroll
                for (int j = 0; j < 4; j++) acc[g][e][j] = 0ull;

        #pragma unroll
        for (int c = 0; c < 8; c++) {
            ulonglong2 hq[4];
            #pragma unroll
            for (int j = 0; j < 4; j++) {
                int b = bb + 8*j;
                int pos = (k0 + kk*32 + c*4) ^ (8*(b & 3));
                hq[j] = *(const ulonglong2*)&hsm[b*PITCH + pos];
            }
            #pragma unroll
            for (int g = 0; g < 4; g++)
                #pragma unroll
                for (int e = 0; e < 2; e++) {
                    int rr = g*8 + 2*p + e;
                    ulonglong2 wq = *(const ulonglong2*)
                        &Wsm[rr*512 + k0 + c*16 + kk*4];
                    #pragma unroll
                    for (int j = 0; j < 4; j++) {
                        fma2(acc[g][e][j], wq.x, hq[j].x);
                        fma2(acc[g][e][j], wq.y, hq[j].y);
                    }
                }
        }

        float av[4][2][4];
        #pragma unroll
        for (int g = 0; g < 4; g++)
            #pragma unroll
            for (int e = 0; e < 2; e++)
                #pragma unroll
                for (int j = 0; j < 4; j++) {
                    float v = collapse2(acc[g][e][j]);
                    v += __shfl_xor_sync(0xffffffffu, v, 8);
                    v += __shfl_xor_sync(0xffffffffu, v, 16);
                    av[g][e][j] = v;
                }

        if (kq > 0 && kk == 0) {
            #pragma unroll
            for (int g = 0; g < 4; g++)
                #pragma unroll
                for (int e = 0; e < 2; e++)
                    #pragma unroll
                    for (int j = 0; j < 4; j++)
                        red[(((kq-1)*4 + p)*8 + g*2 + e)*32 + bb + 8*j]
                            = av[g][e][j];
        }
        __syncthreads();

        if (kq == 0) {
            #pragma unroll
            for (int g = 0; g < 4; g++)
                #pragma unroll
                for (int e = 0; e < 2; e++)
                    #pragma unroll
                    for (int j = 0; j < 4; j++) {
                        float s = av[g][e][j];
                        #pragma unroll
                        for (int jj = 0; jj < 3; jj++)
                            s += red[((jj*4 + p)*8 + g*2 + e)*32 + bb + 8*j];
                        av[g][e][j] = s;
                    }
            #pragma unroll
            for (int e = 0; e < 2; e++)
                #pragma unroll
                for (int j = 0; j < 4; j++) {
                    int b = bb + 8*j;
                    float zi = av[0][e][j] + xwsm[(0*8 + 2*p + e)*32 + b];
                    float zf = av[1][e][j] + xwsm[(1*8 + 2*p + e)*32 + b];
                    float zg = av[2][e][j] + xwsm[(2*8 + 2*p + e)*32 + b];
                    float zo = av[3][e][j] + xwsm[(3*8 + 2*p + e)*32 + b];
                    float cn = sigm(zf)*cst[e][j] + sigm(zi)*tanhf(zg);
                    float hn = sigm(zo)*tanhf(cn);
                    cst[e][j] = cn;
                    if (kk == 0) {
                        const int u = u0 + e;
                        __stcg(&g_cur[d][ph^1][b*H_ + u], hn);
                        __stcg(&g_hT[d][((size_t)txw*H_ + u)*32 + b], hn);
                    }
                }
        }

        __syncthreads();
        if (t < T_ - 1) {
            if (tid == 0) {
                int a = atom_add_acqrel(&g_cnt2[d], 1);
                if (a == 64*t + 63) {
                    st_release(&g_gen2[d], t + 1);
                } else {
                    while (ld_acquire(&g_gen2[d]) <= t) { }
                }
            }
            __syncthreads();
        }
    }
}

// ---------------- 4) output projection feats[b,t,k] -------------------------
__global__ void feats_kernel(const float* __restrict__ Wout,
                             const float* __restrict__ bout)
{
    __shared__ float Ws[32*65];    // [k][jj]
    __shared__ float Rs[64*33];    // [jj][b]

    const int tid = threadIdx.x;
    const int b   = tid >> 5;
    const int k   = tid & 31;
    const int t   = blockIdx.x;

    float acc = 0.0f;

    for (int j0 = 0; j0 < 2*H_; j0 += 64) {
        __syncthreads();
        #pragma unroll
        for (int i = tid; i < 32*64; i += 1024) {
            int kk = i >> 6, jj = i & 63;
            Ws[kk*65 + jj] = Wout[kk * (2*H_) + j0 + jj];
        }
        #pragma unroll
        for (int i = tid; i < 64*32; i += 1024) {
            int jj = i >> 5, bb = i & 31;
            int j = j0 + jj;
            float v = (j < H_)
                ? g_hT[0][((size_t)t*H_ + j      )*32 + bb]
                : g_hT[1][((size_t)t*H_ + (j-H_) )*32 + bb];
            Rs[jj*33 + bb] = v;
        }
        __syncthreads();
        #pragma unroll
        for (int jj = 0; jj < 64; jj++)
            acc += Ws[k*65 + jj] * Rs[jj*33 + b];
    }
    g_feats[((size_t)b*T_ + t) * K_ + k] = acc + bout[k];
}

// ---------------- 5) Viterbi decode + backtrack ------------------------------
__global__ void viterbi_kernel(const float* __restrict__ trans,
                               float* __restrict__ out, int path_base)
{
    __shared__ float tr[32][33];
    const int tid = threadIdx.x;
    tr[tid >> 5][tid & 31] = trans[tid];
    __syncthreads();

    const int b    = tid >> 5;
    const int lane = tid & 31;

    float v = (lane == 30) ? 0.0f : NEG_;   // START = 30

    for (int t = 0; t < T_; t++) {
        float ft = g_feats[(size_t)(b * T_ + t) * K_ + lane];
        float best = -3.4e38f;
        int   bp   = 0;
        float vcur = v;
        #pragma unroll
        for (int p = 0; p < 32; p++) {
            float vp = __shfl_sync(0xffffffffu, vcur, p);
            float s = vp + tr[lane][p];
            if (s > best) { best = s; bp = p; }
        }
        v = best + ft;
        g_bp[(size_t)(t * 32 + b) * 32 + lane] = (unsigned char)bp;
    }

    float term = v + tr[31][lane];           // STOP = 31

    float bv = term; int bi = lane;
    #pragma unroll
    for (int off = 16; off > 0; off >>= 1) {
        float ov = __shfl_down_sync(0xffffffffu, bv, off);
        int   oi = __shfl_down_sync(0xffffffffu, bi, off);
        if (ov > bv || (ov == bv && oi < bi)) { bv = ov; bi = oi; }
    }
    bi = __shfl_sync(0xffffffffu, bi, 0);
    bv = __shfl_sync(0xffffffffu, bv, 0);

    if (lane == 0) {
        if (path_base > 0) out[b] = bv;
        int tag = bi;
        for (int t = T_ - 1; t >= 0; t--) {
            out[path_base + b * T_ + t] = (float)tag;
            tag = g_bp[(size_t)(t * 32 + b) * 32 + tag];
        }
    }
}

// ---------------- launch -----------------------------------------------------
extern "C" void kernel_launch(void* const* d_in, const int* in_sizes, int n_in,
                              void* d_out, int out_size)
{
    int unit = 0;
    for (int i = 0; i < n_in; i++) {
        if (in_sizes[i] == 12800000) { unit = 1; break; }
        if (in_sizes[i] == 51200000) { unit = 4; break; }
    }

    int i_sent = -1, i_emb = -1, i_bout = -1, i_tr = -1, sent64 = 0;
    int gih[2], nih = 0, ghh[2], nhh = 0, g2i[2], n2 = 0, g3i[3], n3 = 0;
    if (unit) {
        for (int i = 0; i < n_in; i++) {
            const int s = in_sizes[i] / unit;
            if      (s == 8192)     { if (i_sent < 0) { i_sent = i; sent64 = 0; } }
            else if (s == 16384)    { if (i_sent < 0) { i_sent = i; sent64 = 1; } }
            else if (s == 12800000) { if (i_emb  < 0) i_emb  = i; }
            else if (s == 32)       { if (i_bout < 0) i_bout = i; }
            else if (s == 1024)     { if (i_tr   < 0) i_tr   = i; }
            else if (s == 524288)   { if (nih < 2) gih[nih++] = i; }
            else if (s == 1048576)  { if (nhh < 2) ghh[nhh++] = i; }
            else if (s == 2048)     { if (n2  < 2) g2i[n2++]  = i; }
            else if (s == 32768)    { if (n3  < 3) g3i[n3++]  = i; }
        }
    }
    const int out_elems = (unit == 4) ? out_size / 4 : out_size;

    if (!unit || i_sent < 0 || i_emb < 0 || i_bout < 0 || i_tr < 0 ||
        nih != 2 || nhh != 2 || n2 != 2 || n3 != 3) {
        int n = out_size > 0 ? out_size : 1;
        fill_out<<<(n + 255) / 256, 256>>>((float*)d_out, n, 1.0e6f);
        return;
    }

    int I_Wihf, I_Whhf, I_Wihb, I_Whhb, I_bf, I_bb, I_Wout, I_h0, I_c0;
    if (i_sent < i_emb) {   // dict order
        I_Wihf = gih[0]; I_Wihb = gih[1];
        I_Whhf = ghh[0]; I_Whhb = ghh[1];
        I_bf   = g2i[0]; I_bb   = g2i[1];
        I_Wout = g3i[0]; I_h0   = g3i[1]; I_c0 = g3i[2];
    } else {                // name-sorted order
        I_Whhb = ghh[0]; I_Whhf = ghh[1];
        I_Wihb = gih[0]; I_Wihf = gih[1];
        I_bb   = g2i[0]; I_bf   = g2i[1];
        I_Wout = g3i[0]; I_c0   = g3i[1]; I_h0 = g3i[2];
    }

    const void*  sentence = d_in[i_sent];
    const float* emb      = (const float*)d_in[i_emb];
    const float* W_ih_f   = (const float*)d_in[I_Wihf];
    const float* W_hh_f   = (const float*)d_in[I_Whhf];
    const float* b_f      = (const float*)d_in[I_bf];
    const float* W_ih_b   = (const float*)d_in[I_Wihb];
    const float* W_hh_b   = (const float*)d_in[I_Whhb];
    const float* b_b      = (const float*)d_in[I_bb];
    const float* W_out    = (const float*)d_in[I_Wout];
    const float* b_out    = (const float*)d_in[i_bout];
    const float* trans    = (const float*)d_in[i_tr];
    const float* h0       = (const float*)d_in[I_h0];
    const float* c0       = (const float*)d_in[I_c0];
    float* out = (float*)d_out;

    const int path_base = (out_elems >= B_ + B_*T_) ? B_ : 0;

    const int SMEM_G = (4096 + 128*129) * 4;                          // 82432 B
    const int SMEM_P = (32*512 + 32*PITCH + 3*4*8*32 + 32*32) * 4;    // 147968 B
    cudaFuncSetAttribute(gemm_xw,
                         cudaFuncAttributeMaxDynamicSharedMemorySize, SMEM_G);
    cudaFuncSetAttribute(lstm_persist,
                         cudaFuncAttributeMaxDynamicSharedMemorySize, SMEM_P);

    gemm_xw<<<dim3(32, 64), 256, SMEM_G>>>(sentence, sent64, emb,
                                           W_ih_f, W_ih_b, b_f, b_b);
    init_state<<<64, 512>>>(h0);
    lstm_persist<<<128, 512, SMEM_P>>>(W_hh_f, W_hh_b, c0);
    feats_kernel<<<T_, 1024>>>(W_out, b_out);
    viterbi_kernel<<<1, 1024>>>(trans, out, path_base);
}